// round 7
// baseline (speedup 1.0000x reference)
#include <cuda_runtime.h>
#include <cuda_fp16.h>
#include <cstdint>

#define B_  256
#define T_  512
#define I_  24
#define H_  128
#define G_  512           // 4*H
#define BT_ (B_*T_)       // 131072
#define MB_ 8             // batch rows per scan cluster
#define HAS_ 136          // hA row stride in halves (128 + 8 pad)
#define SAS_ 40           // GEMM smem row stride in halves (32 + 8 pad)

static const size_t Y1SZ_ = (size_t)BT_ * 2 * H_;   // 33,554,432

// ---------------- scratch (no cudaMalloc allowed) ----------------
// gx fp32, pre-scaled by 0.5 for gates i,f,o. Layout [t][b][j], A-rows t-major.
__device__ float  g_gx[2][(size_t)BT_ * G_];        // 2 x 256 MB
__device__ __half g_y0h[(size_t)BT_ * 2 * H_];      // 64 MB, rows r' = t*B + b
__device__ __half g_xh[(size_t)BT_ * 32];           // x padded 24->32, rows r' = t*B + b
__device__ __half g_w0h[2][G_ * 32];                // w_ih layer0 padded, fp16
__device__ __half g_w1h[2][G_ * 256];               // w_ih layer1, fp16

__device__ __forceinline__ float tanhap(float x) {
    float y; asm("tanh.approx.f32 %0, %1;" : "=f"(y) : "f"(x)); return y;
}
__device__ __forceinline__ void cp16(unsigned dst, const void* src) {
    asm volatile("cp.async.ca.shared.global [%0], [%1], 16;" :: "r"(dst), "l"(src));
}
__device__ __forceinline__ unsigned ctarank() {
    unsigned r; asm("mov.u32 %0, %%cluster_ctarank;" : "=r"(r)); return r;
}
__device__ __forceinline__ void st_cluster_u32(unsigned laddr, unsigned peer, unsigned val) {
    asm volatile("{\n\t.reg .b32 ra;\n\tmapa.shared::cluster.u32 ra, %0, %1;\n\t"
                 "st.shared::cluster.b32 [ra], %2;\n\t}"
                 :: "r"(laddr), "r"(peer), "r"(val) : "memory");
}

// ---------------- conversion kernels ----------------
__global__ void conv_x_kernel(const float* __restrict__ x) {
    int idx = blockIdx.x * 256 + threadIdx.x;
    if (idx < BT_ * 32) {
        int r = idx >> 5, i = idx & 31;       // r' = t*256 + b
        int b = r & 255, t = r >> 8;
        g_xh[idx] = (i < I_) ? __float2half(x[((size_t)b * T_ + t) * I_ + i]) : __float2half(0.f);
    }
}

__global__ void conv_w_kernel(const float* __restrict__ w0f, const float* __restrict__ w0b,
                              const float* __restrict__ w1f, const float* __restrict__ w1b) {
    int idx = blockIdx.x * 256 + threadIdx.x;
    if (idx < 2 * G_ * 32) {
        int d = idx / (G_ * 32); int p = idx % (G_ * 32);
        int j = p >> 5, i = p & 31;
        const float* w = d ? w0b : w0f;
        g_w0h[d][p] = (i < I_) ? __float2half(w[j * I_ + i]) : __float2half(0.f);
    } else {
        int q = idx - 2 * G_ * 32;
        if (q < 2 * G_ * 256) {
            int d = q / (G_ * 256); int p = q % (G_ * 256);
            const float* w = d ? w1b : w1f;
            g_w1h[d][p] = __float2half(w[p]);
        }
    }
}

// ---------------- pipelined input GEMM (unchanged, verified) ----------------
__global__ __launch_bounds__(256) void gemm_gx_kernel(
    const float* __restrict__ biasf, const float* __restrict__ biasb, int K)
{
    __shared__ __half sA[2][128 * SAS_];
    __shared__ __half sW[2][128 * SAS_];

    const int dir = blockIdx.z;
    const __half* __restrict__ A = (K == 32) ? g_xh : g_y0h;
    const __half* __restrict__ W = (K == 32) ? g_w0h[dir] : g_w1h[dir];
    const float* __restrict__ bias = dir ? biasb : biasf;
    float* __restrict__ gx = g_gx[dir];

    const int tid  = threadIdx.x;
    const int lane = tid & 31;
    const int warp = tid >> 5;
    const int warpM = warp & 3;
    const int warpN = warp >> 2;
    const int g4 = lane >> 2;
    const int tg = lane & 3;
    const int mblk = blockIdx.x * 128;
    const int nblk = blockIdx.y * 128;
    const int nk = K >> 5;

    const unsigned sA_base = (unsigned)__cvta_generic_to_shared(sA);
    const unsigned sW_base = (unsigned)__cvta_generic_to_shared(sW);

    const int lrow = tid >> 2;
    const int lseg = tid & 3;

    auto load_stage = [&](int ks, int buf) {
        #pragma unroll
        for (int rr = 0; rr < 2; rr++) {
            int r = lrow + rr * 64;
            const __half* srcA = A + (size_t)(mblk + r) * K + ks * 32 + lseg * 8;
            const __half* srcW = W + (size_t)(nblk + r) * K + ks * 32 + lseg * 8;
            unsigned off = (unsigned)(buf * 128 * SAS_ + r * SAS_ + lseg * 8) * 2;
            cp16(sA_base + off, srcA);
            cp16(sW_base + off, srcW);
        }
        asm volatile("cp.async.commit_group;");
    };

    float acc[2][8][4];
    #pragma unroll
    for (int mf = 0; mf < 2; mf++)
        #pragma unroll
        for (int nf = 0; nf < 8; nf++)
            #pragma unroll
            for (int q = 0; q < 4; q++) acc[mf][nf][q] = 0.f;

    load_stage(0, 0);

    const unsigned lmA0 = sA_base + ((warpM * 32 + (lane & 15)) * SAS_ + (lane >> 4) * 8) * 2;
    const unsigned lmW0 = sW_base + ((warpN * 64 + (lane & 7)) * SAS_ + ((lane >> 3) & 1) * 8) * 2;

    for (int ks = 0; ks < nk; ks++) {
        const int buf = ks & 1;
        if (ks + 1 < nk) {
            load_stage(ks + 1, buf ^ 1);
            asm volatile("cp.async.wait_group 1;");
        } else {
            asm volatile("cp.async.wait_group 0;");
        }
        __syncthreads();

        const unsigned aBuf = lmA0 + buf * 128 * SAS_ * 2;
        const unsigned wBuf = lmW0 + buf * 128 * SAS_ * 2;

        #pragma unroll
        for (int kk = 0; kk < 2; kk++) {
            unsigned a[2][4];
            #pragma unroll
            for (int mf = 0; mf < 2; mf++) {
                asm volatile("ldmatrix.sync.aligned.m8n8.x4.shared.b16 {%0,%1,%2,%3}, [%4];"
                    : "=r"(a[mf][0]), "=r"(a[mf][1]), "=r"(a[mf][2]), "=r"(a[mf][3])
                    : "r"(aBuf + (mf * 16 * SAS_ + kk * 16) * 2));
            }
            #pragma unroll
            for (int nf = 0; nf < 8; nf++) {
                unsigned b0, b1;
                asm volatile("ldmatrix.sync.aligned.m8n8.x2.shared.b16 {%0,%1}, [%2];"
                    : "=r"(b0), "=r"(b1)
                    : "r"(wBuf + (nf * 8 * SAS_ + kk * 16) * 2));
                #pragma unroll
                for (int mf = 0; mf < 2; mf++) {
                    asm volatile(
                        "mma.sync.aligned.m16n8k16.row.col.f32.f16.f16.f32 "
                        "{%0,%1,%2,%3}, {%4,%5,%6,%7}, {%8,%9}, {%0,%1,%2,%3};"
                        : "+f"(acc[mf][nf][0]), "+f"(acc[mf][nf][1]),
                          "+f"(acc[mf][nf][2]), "+f"(acc[mf][nf][3])
                        : "r"(a[mf][0]), "r"(a[mf][1]), "r"(a[mf][2]), "r"(a[mf][3]),
                          "r"(b0), "r"(b1));
                }
            }
        }
        __syncthreads();
    }

    const int t = mblk >> 8;
    #pragma unroll
    for (int mf = 0; mf < 2; mf++) {
        int m = warpM * 32 + mf * 16 + g4;
        int b = (mblk & 255) + m;
        #pragma unroll
        for (int nf = 0; nf < 8; nf++) {
            int n0 = nblk + warpN * 64 + nf * 8 + tg * 2;
            float sc = ((n0 >> 7) == 2) ? 1.f : 0.5f;
            float bv0 = bias[n0], bv1 = bias[n0 + 1];
            *(float2*)&gx[((size_t)t * B_ + b)     * G_ + n0] =
                make_float2(sc * (acc[mf][nf][0] + bv0), sc * (acc[mf][nf][1] + bv1));
            *(float2*)&gx[((size_t)t * B_ + b + 8) * G_ + n0] =
                make_float2(sc * (acc[mf][nf][2] + bv0), sc * (acc[mf][nf][3] + bv1));
        }
    }
}

// ---------------- cluster-split tensor-core recurrent scan ----------------
// grid (2, 32, 2), cluster (2,1,1): blockIdx.x = hidden-col half, y = batch
// group (8 rows), z = direction. 256 threads / 8 warps per CTA.
// Each CTA computes gates[8, 256] (its 64 hidden cols x 4 gates) from the FULL
// h[16,128] in its own hA; computes h for its 64 cols; writes h to its own AND
// the peer's hA write-buffer via st.shared::cluster; barrier.cluster per step.
// Inner arithmetic identical to the verified single-CTA kernel.
__global__ __launch_bounds__(256) __cluster_dims__(2, 1, 1)
void lstm_scan_mma(
    const float* __restrict__ whhf, const float* __restrict__ whhb,
    float* __restrict__ y1, float* __restrict__ hn, float* __restrict__ cn, int layer)
{
    __shared__ __half hA[2 * 16 * HAS_];  // 8704 B, two buffers (full 128 cols)

    const int tid  = threadIdx.x;
    const int lane = tid & 31;
    const int w    = tid >> 5;            // warp 0..7 -> 8-col slice of this half
    const int half = blockIdx.x;
    const int dir  = blockIdx.z;
    const int b0   = blockIdx.y * MB_;
    const int g4 = lane >> 2, tg = lane & 3;
    const unsigned rank = ctarank();
    const unsigned peer = rank ^ 1u;
    const float* __restrict__ whh = dir ? whhb : whhf;
    const float* __restrict__ gx  = g_gx[dir];

    // preload w_hh fragments: Bf[ks][g] covers gate cols j = g*128 + half*64 + 8w .. +8
    unsigned Bf[8][4][2];
    #pragma unroll
    for (int ks = 0; ks < 8; ks++)
        #pragma unroll
        for (int g = 0; g < 4; g++) {
            const float* p = whh + (size_t)(g * 128 + half * 64 + 8 * w + g4) * H_ + ks * 16 + tg * 2;
            float2 v0 = *(const float2*)p;
            float2 v1 = *(const float2*)(p + 8);
            __half2 p0 = __floats2half2_rn(v0.x, v0.y);
            __half2 p1 = __floats2half2_rn(v1.x, v1.y);
            Bf[ks][g][0] = *(unsigned*)&p0;
            Bf[ks][g][1] = *(unsigned*)&p1;
        }

    for (int p = tid; p < 2 * 16 * HAS_; p += 256) hA[p] = __float2half(0.f);

    const int col  = half * 64 + 8 * w + 2 * tg;   // global hidden col (2 per thread)
    const int brow = b0 + g4;                      // batch row owned in cell phase
    float cst0 = 0.f, cst1 = 0.f;
    float h0 = 0.f, h1 = 0.f;

    const unsigned hA_base = (unsigned)__cvta_generic_to_shared(hA);
    const unsigned lmA = hA_base + (((lane & 15) * HAS_) + ((lane >> 4) * 8)) * 2;
    const unsigned BUFB = 16 * HAS_ * 2;

    // cluster sync: both CTAs' hA zeroed before any peer store can land
    asm volatile("barrier.cluster.arrive.aligned;" ::: "memory");
    asm volatile("barrier.cluster.wait.aligned;" ::: "memory");

    // prefetch gx for first step
    float2 gxc0, gxc1, gxc2, gxc3;
    {
        int t0 = dir ? (T_ - 1) : 0;
        const float* p = gx + ((size_t)t0 * B_ + brow) * G_ + col;
        gxc0 = *(const float2*)(p);
        gxc1 = *(const float2*)(p + 128);
        gxc2 = *(const float2*)(p + 256);
        gxc3 = *(const float2*)(p + 384);
    }

    for (int s = 0; s < T_; s++) {
        const int t = dir ? (T_ - 1 - s) : s;
        const int rb = s & 1;
        const unsigned lm = lmA + rb * BUFB;

        // prefetch next step's gx
        float2 gxn0, gxn1, gxn2, gxn3;
        if (s + 1 < T_) {
            int tn = dir ? (T_ - 2 - s) : (s + 1);
            const float* p = gx + ((size_t)tn * B_ + brow) * G_ + col;
            gxn0 = *(const float2*)(p);
            gxn1 = *(const float2*)(p + 128);
            gxn2 = *(const float2*)(p + 256);
            gxn3 = *(const float2*)(p + 384);
        } else {
            gxn0 = gxn1 = gxn2 = gxn3 = make_float2(0.f, 0.f);
        }

        // ---- gates = hA[rb] @ Whh^T (this CTA's 256 gate cols) ----
        float c[4][4];
        #pragma unroll
        for (int g = 0; g < 4; g++)
            #pragma unroll
            for (int q = 0; q < 4; q++) c[g][q] = 0.f;

        #pragma unroll
        for (int ks = 0; ks < 8; ks++) {
            unsigned a0, a1, a2, a3;
            asm volatile("ldmatrix.sync.aligned.m8n8.x4.shared.b16 {%0,%1,%2,%3}, [%4];"
                : "=r"(a0), "=r"(a1), "=r"(a2), "=r"(a3) : "r"(lm + ks * 32));
            #pragma unroll
            for (int g = 0; g < 4; g++) {
                asm volatile(
                    "mma.sync.aligned.m16n8k16.row.col.f32.f16.f16.f32 "
                    "{%0,%1,%2,%3}, {%4,%5,%6,%7}, {%8,%9}, {%0,%1,%2,%3};"
                    : "+f"(c[g][0]), "+f"(c[g][1]), "+f"(c[g][2]), "+f"(c[g][3])
                    : "r"(a0), "r"(a1), "r"(a2), "r"(a3),
                      "r"(Bf[ks][g][0]), "r"(Bf[ks][g][1]));
            }
        }

        // ---- in-register LSTM cell (2 cells per thread) ----
        float ii0 = fmaf(tanhap(fmaf(c[0][0], 0.5f, gxc0.x)), 0.5f, 0.5f);
        float ii1 = fmaf(tanhap(fmaf(c[0][1], 0.5f, gxc0.y)), 0.5f, 0.5f);
        float ff0 = fmaf(tanhap(fmaf(c[1][0], 0.5f, gxc1.x)), 0.5f, 0.5f);
        float ff1 = fmaf(tanhap(fmaf(c[1][1], 0.5f, gxc1.y)), 0.5f, 0.5f);
        float gg0 = tanhap(c[2][0] + gxc2.x);
        float gg1 = tanhap(c[2][1] + gxc2.y);
        float oo0 = fmaf(tanhap(fmaf(c[3][0], 0.5f, gxc3.x)), 0.5f, 0.5f);
        float oo1 = fmaf(tanhap(fmaf(c[3][1], 0.5f, gxc3.y)), 0.5f, 0.5f);

        cst0 = fmaf(ff0, cst0, ii0 * gg0);
        cst1 = fmaf(ff1, cst1, ii1 * gg1);
        h0 = oo0 * tanhap(cst0);
        h1 = oo1 * tanhap(cst1);

        __half2 hp = __floats2half2_rn(h0, h1);
        const unsigned hpu = *(const unsigned*)&hp;
        const unsigned wboff = (unsigned)(((rb ^ 1) * 16 + g4) * HAS_ + col) * 2;
        *(__half2*)((char*)hA + wboff) = hp;            // local write-buffer
        st_cluster_u32(hA_base + wboff, peer, hpu);     // peer's write-buffer

        if (layer) {
            *(float2*)&y1[((size_t)brow * T_ + t) * (2 * H_) + dir * H_ + col] = make_float2(h0, h1);
        } else {
            *(__half2*)&g_y0h[((size_t)t * B_ + brow) * (2 * H_) + dir * H_ + col] = hp;
        }

        gxc0 = gxn0; gxc1 = gxn1; gxc2 = gxn2; gxc3 = gxn3;

        // both CTAs' h writes (local + remote) visible before next step's reads
        asm volatile("barrier.cluster.arrive.aligned;" ::: "memory");
        asm volatile("barrier.cluster.wait.aligned;" ::: "memory");
    }

    const int d = layer * 2 + dir;
    const size_t so = ((size_t)d * B_ + brow) * H_ + col;
    *(float2*)&hn[so] = make_float2(h0, h1);
    *(float2*)&cn[so] = make_float2(cst0, cst1);
}

// ---------------- launch ----------------
extern "C" void kernel_launch(void* const* d_in, const int* in_sizes, int n_in,
                              void* d_out, int out_size) {
    const float* x     = (const float*)d_in[0];
    const float* wih0f = (const float*)d_in[1];
    const float* whh0f = (const float*)d_in[2];
    const float* b0f   = (const float*)d_in[3];
    const float* wih0b = (const float*)d_in[4];
    const float* whh0b = (const float*)d_in[5];
    const float* b0b   = (const float*)d_in[6];
    const float* wih1f = (const float*)d_in[7];
    const float* whh1f = (const float*)d_in[8];
    const float* b1f   = (const float*)d_in[9];
    const float* wih1b = (const float*)d_in[10];
    const float* whh1b = (const float*)d_in[11];
    const float* b1b   = (const float*)d_in[12];
    (void)in_sizes; (void)n_in; (void)out_size;

    float* out = (float*)d_out;
    float* y1 = out;
    float* hn = out + Y1SZ_;
    float* cn = hn + 4 * B_ * H_;

    // fp16 conversions
    conv_x_kernel<<<(BT_ * 32 + 255) / 256, 256>>>(x);
    conv_w_kernel<<<(2 * G_ * 32 + 2 * G_ * 256 + 255) / 256, 256>>>(wih0f, wih0b, wih1f, wih1b);

    // layer 0
    gemm_gx_kernel<<<dim3(BT_ / 128, G_ / 128, 2), 256>>>(b0f, b0b, 32);
    lstm_scan_mma<<<dim3(2, B_ / MB_, 2), 256>>>(whh0f, whh0b, y1, hn, cn, 0);

    // layer 1
    gemm_gx_kernel<<<dim3(BT_ / 128, G_ / 128, 2), 256>>>(b1f, b1b, 256);
    lstm_scan_mma<<<dim3(2, B_ / MB_, 2), 256>>>(whh1f, whh1b, y1, hn, cn, 1);
}

// round 8
// speedup vs baseline: 1.4750x; 1.4750x over previous
#include <cuda_runtime.h>
#include <cuda_fp16.h>
#include <cstdint>

#define B_  256
#define T_  512
#define I_  24
#define H_  128
#define G_  512           // 4*H
#define BT_ (B_*T_)       // 131072
#define MB_ 8             // batch rows per scan block
#define HAS_ 136          // hA row stride in halves (128 + 8 pad)
#define SAS_ 40           // GEMM smem row stride in halves (32 + 8 pad)

static const size_t Y1SZ_ = (size_t)BT_ * 2 * H_;   // 33,554,432

// ---------------- scratch (no cudaMalloc allowed) ----------------
// gx fp32, pre-scaled by 0.5 for gates i,f,o. Layout [t][b][j], A-rows t-major.
__device__ float  g_gx[2][(size_t)BT_ * G_];        // 2 x 256 MB
__device__ __half g_y0h[(size_t)BT_ * 2 * H_];      // 64 MB, rows r' = t*B + b
__device__ __half g_xh[(size_t)BT_ * 32];           // x padded 24->32, rows r' = t*B + b
__device__ __half g_w0h[2][G_ * 32];                // w_ih layer0 padded, fp16
__device__ __half g_w1h[2][G_ * 256];               // w_ih layer1, fp16

__device__ __forceinline__ float tanhap(float x) {
    float y; asm("tanh.approx.f32 %0, %1;" : "=f"(y) : "f"(x)); return y;
}
__device__ __forceinline__ void cp16(unsigned dst, const void* src) {
    asm volatile("cp.async.ca.shared.global [%0], [%1], 16;" :: "r"(dst), "l"(src));
}

// ---------------- conversion kernels ----------------
__global__ void conv_x_kernel(const float* __restrict__ x) {
    int idx = blockIdx.x * 256 + threadIdx.x;
    if (idx < BT_ * 32) {
        int r = idx >> 5, i = idx & 31;       // r' = t*256 + b
        int b = r & 255, t = r >> 8;
        g_xh[idx] = (i < I_) ? __float2half(x[((size_t)b * T_ + t) * I_ + i]) : __float2half(0.f);
    }
}

__global__ void conv_w_kernel(const float* __restrict__ w0f, const float* __restrict__ w0b,
                              const float* __restrict__ w1f, const float* __restrict__ w1b) {
    int idx = blockIdx.x * 256 + threadIdx.x;
    if (idx < 2 * G_ * 32) {
        int d = idx / (G_ * 32); int p = idx % (G_ * 32);
        int j = p >> 5, i = p & 31;
        const float* w = d ? w0b : w0f;
        g_w0h[d][p] = (i < I_) ? __float2half(w[j * I_ + i]) : __float2half(0.f);
    } else {
        int q = idx - 2 * G_ * 32;
        if (q < 2 * G_ * 256) {
            int d = q / (G_ * 256); int p = q % (G_ * 256);
            const float* w = d ? w1b : w1f;
            g_w1h[d][p] = __float2half(w[p]);
        }
    }
}

// ---------------- pipelined input GEMM (R6 verbatim, verified) ----------------
__global__ __launch_bounds__(256) void gemm_gx_kernel(
    const float* __restrict__ biasf, const float* __restrict__ biasb, int K)
{
    __shared__ __half sA[2][128 * SAS_];
    __shared__ __half sW[2][128 * SAS_];

    const int dir = blockIdx.z;
    const __half* __restrict__ A = (K == 32) ? g_xh : g_y0h;
    const __half* __restrict__ W = (K == 32) ? g_w0h[dir] : g_w1h[dir];
    const float* __restrict__ bias = dir ? biasb : biasf;
    float* __restrict__ gx = g_gx[dir];

    const int tid  = threadIdx.x;
    const int lane = tid & 31;
    const int warp = tid >> 5;
    const int warpM = warp & 3;
    const int warpN = warp >> 2;
    const int g4 = lane >> 2;
    const int tg = lane & 3;
    const int mblk = blockIdx.x * 128;
    const int nblk = blockIdx.y * 128;
    const int nk = K >> 5;

    const unsigned sA_base = (unsigned)__cvta_generic_to_shared(sA);
    const unsigned sW_base = (unsigned)__cvta_generic_to_shared(sW);

    const int lrow = tid >> 2;
    const int lseg = tid & 3;

    auto load_stage = [&](int ks, int buf) {
        #pragma unroll
        for (int rr = 0; rr < 2; rr++) {
            int r = lrow + rr * 64;
            const __half* srcA = A + (size_t)(mblk + r) * K + ks * 32 + lseg * 8;
            const __half* srcW = W + (size_t)(nblk + r) * K + ks * 32 + lseg * 8;
            unsigned off = (unsigned)(buf * 128 * SAS_ + r * SAS_ + lseg * 8) * 2;
            cp16(sA_base + off, srcA);
            cp16(sW_base + off, srcW);
        }
        asm volatile("cp.async.commit_group;");
    };

    float acc[2][8][4];
    #pragma unroll
    for (int mf = 0; mf < 2; mf++)
        #pragma unroll
        for (int nf = 0; nf < 8; nf++)
            #pragma unroll
            for (int q = 0; q < 4; q++) acc[mf][nf][q] = 0.f;

    load_stage(0, 0);

    const unsigned lmA0 = sA_base + ((warpM * 32 + (lane & 15)) * SAS_ + (lane >> 4) * 8) * 2;
    const unsigned lmW0 = sW_base + ((warpN * 64 + (lane & 7)) * SAS_ + ((lane >> 3) & 1) * 8) * 2;

    for (int ks = 0; ks < nk; ks++) {
        const int buf = ks & 1;
        if (ks + 1 < nk) {
            load_stage(ks + 1, buf ^ 1);
            asm volatile("cp.async.wait_group 1;");
        } else {
            asm volatile("cp.async.wait_group 0;");
        }
        __syncthreads();

        const unsigned aBuf = lmA0 + buf * 128 * SAS_ * 2;
        const unsigned wBuf = lmW0 + buf * 128 * SAS_ * 2;

        #pragma unroll
        for (int kk = 0; kk < 2; kk++) {
            unsigned a[2][4];
            #pragma unroll
            for (int mf = 0; mf < 2; mf++) {
                asm volatile("ldmatrix.sync.aligned.m8n8.x4.shared.b16 {%0,%1,%2,%3}, [%4];"
                    : "=r"(a[mf][0]), "=r"(a[mf][1]), "=r"(a[mf][2]), "=r"(a[mf][3])
                    : "r"(aBuf + (mf * 16 * SAS_ + kk * 16) * 2));
            }
            #pragma unroll
            for (int nf = 0; nf < 8; nf++) {
                unsigned b0, b1;
                asm volatile("ldmatrix.sync.aligned.m8n8.x2.shared.b16 {%0,%1}, [%2];"
                    : "=r"(b0), "=r"(b1)
                    : "r"(wBuf + (nf * 8 * SAS_ + kk * 16) * 2));
                #pragma unroll
                for (int mf = 0; mf < 2; mf++) {
                    asm volatile(
                        "mma.sync.aligned.m16n8k16.row.col.f32.f16.f16.f32 "
                        "{%0,%1,%2,%3}, {%4,%5,%6,%7}, {%8,%9}, {%0,%1,%2,%3};"
                        : "+f"(acc[mf][nf][0]), "+f"(acc[mf][nf][1]),
                          "+f"(acc[mf][nf][2]), "+f"(acc[mf][nf][3])
                        : "r"(a[mf][0]), "r"(a[mf][1]), "r"(a[mf][2]), "r"(a[mf][3]),
                          "r"(b0), "r"(b1));
                }
            }
        }
        __syncthreads();
    }

    const int t = mblk >> 8;
    #pragma unroll
    for (int mf = 0; mf < 2; mf++) {
        int m = warpM * 32 + mf * 16 + g4;
        int b = (mblk & 255) + m;
        #pragma unroll
        for (int nf = 0; nf < 8; nf++) {
            int n0 = nblk + warpN * 64 + nf * 8 + tg * 2;
            float sc = ((n0 >> 7) == 2) ? 1.f : 0.5f;
            float bv0 = bias[n0], bv1 = bias[n0 + 1];
            *(float2*)&gx[((size_t)t * B_ + b)     * G_ + n0] =
                make_float2(sc * (acc[mf][nf][0] + bv0), sc * (acc[mf][nf][1] + bv1));
            *(float2*)&gx[((size_t)t * B_ + b + 8) * G_ + n0] =
                make_float2(sc * (acc[mf][nf][2] + bv0), sc * (acc[mf][nf][3] + bv1));
        }
    }
}

// ---------------- transposed tensor-core recurrent scan ----------------
// grid (32, 2), 512 threads, single CTA per block (cluster reverted — too slow).
// gates^T[512,8] = Whh @ h^T: M = gate cols (16 real), N = batch (8 real), no
// padding waste -> 16 MMA/warp/step (was 32). W rows PERMUTED per m16 tile:
//   tile0 rows 0-7 = gate i cols [8w,8w+8), rows 8-15 = gate f same cols
//   tile1 rows 0-7 = gate g,               rows 8-15 = gate o
// so thread (g4,tg) ends up holding ALL 4 gates of hidden col 8w+g4 for batch
// rows 2tg, 2tg+1 -> cell update fully in-warp, one barrier/step.
// hA = h[8 batch][128 cols] fp16, double-buffered (read s&1, write (s&1)^1).
__global__ __launch_bounds__(512) void lstm_scan_mma(
    const float* __restrict__ whhf, const float* __restrict__ whhb,
    float* __restrict__ y1, float* __restrict__ hn, float* __restrict__ cn, int layer)
{
    __shared__ __half hA[2 * 8 * HAS_];   // 4352 B, two buffers

    const int tid  = threadIdx.x;
    const int lane = tid & 31;
    const int w    = tid >> 5;            // warp 0..15 -> hidden cols [8w, 8w+8)
    const int dir  = blockIdx.y;
    const int b0   = blockIdx.x * MB_;
    const int g4 = lane >> 2, tg = lane & 3;
    const float* __restrict__ whh = dir ? whhb : whhf;
    const float* __restrict__ gx  = g_gx[dir];

    // preload permuted W fragments: Af[ks][tile][4]
    // tile t: rows 0-7 = gate 2t, rows 8-15 = gate 2t+1, cols = hidden [8w,8w+8)
    unsigned Af[8][2][4];
    #pragma unroll
    for (int ks = 0; ks < 8; ks++)
        #pragma unroll
        for (int tl = 0; tl < 2; tl++) {
            const float* pA = whh + (size_t)((2 * tl)     * 128 + 8 * w + g4) * H_ + ks * 16 + tg * 2;
            const float* pB = whh + (size_t)((2 * tl + 1) * 128 + 8 * w + g4) * H_ + ks * 16 + tg * 2;
            float2 vA0 = *(const float2*)pA;       // a0: row g4   (gate 2t),  k 2tg
            float2 vB0 = *(const float2*)pB;       // a1: row g4+8 (gate 2t+1),k 2tg
            float2 vA1 = *(const float2*)(pA + 8); // a2: row g4,   k 2tg+8
            float2 vB1 = *(const float2*)(pB + 8); // a3: row g4+8, k 2tg+8
            __half2 h0 = __floats2half2_rn(vA0.x, vA0.y);
            __half2 h1 = __floats2half2_rn(vB0.x, vB0.y);
            __half2 h2 = __floats2half2_rn(vA1.x, vA1.y);
            __half2 h3 = __floats2half2_rn(vB1.x, vB1.y);
            Af[ks][tl][0] = *(unsigned*)&h0;
            Af[ks][tl][1] = *(unsigned*)&h1;
            Af[ks][tl][2] = *(unsigned*)&h2;
            Af[ks][tl][3] = *(unsigned*)&h3;
        }

    for (int p = tid; p < 2 * 8 * HAS_; p += 512) hA[p] = __float2half(0.f);

    const int hc    = 8 * w + g4;         // this thread's hidden col
    const int brow0 = b0 + 2 * tg;        // two batch rows owned
    const int brow1 = brow0 + 1;
    float cst0 = 0.f, cst1 = 0.f;
    float h0 = 0.f, h1 = 0.f;

    const unsigned hA_base = (unsigned)__cvta_generic_to_shared(hA);
    // ldmatrix.x2 B source: lanes 0-7 -> rows 0-7 cols [0:8), lanes 8-15 -> rows 0-7 cols [8:16)
    const unsigned lmB = hA_base + (((lane & 7) * HAS_) + (((lane >> 3) & 1) * 8)) * 2;
    const unsigned BUFB = 8 * HAS_ * 2;

    __syncthreads();

    // prefetch gx for first step (8 scalars: 2 batch rows x 4 gates at col hc)
    float xi0, xi1, xf0, xf1, xg0, xg1, xo0, xo1;
    {
        int t0 = dir ? (T_ - 1) : 0;
        const float* p0 = gx + ((size_t)t0 * B_ + brow0) * G_ + hc;
        const float* p1 = gx + ((size_t)t0 * B_ + brow1) * G_ + hc;
        xi0 = p0[0];   xi1 = p1[0];
        xf0 = p0[128]; xf1 = p1[128];
        xg0 = p0[256]; xg1 = p1[256];
        xo0 = p0[384]; xo1 = p1[384];
    }

    for (int s = 0; s < T_; s++) {
        const int t = dir ? (T_ - 1 - s) : s;
        const int rb = s & 1;
        const unsigned lm = lmB + rb * BUFB;
        __half* hw = hA + (rb ^ 1) * 8 * HAS_;

        // prefetch next step's gx
        float ni0, ni1, nf0, nf1, ng0, ng1, no0, no1;
        if (s + 1 < T_) {
            int tn = dir ? (T_ - 2 - s) : (s + 1);
            const float* p0 = gx + ((size_t)tn * B_ + brow0) * G_ + hc;
            const float* p1 = gx + ((size_t)tn * B_ + brow1) * G_ + hc;
            ni0 = p0[0];   ni1 = p1[0];
            nf0 = p0[128]; nf1 = p1[128];
            ng0 = p0[256]; ng1 = p1[256];
            no0 = p0[384]; no1 = p1[384];
        } else {
            ni0 = ni1 = nf0 = nf1 = ng0 = ng1 = no0 = no1 = 0.f;
        }

        // ---- gates^T = W @ h^T : c0 = {i(d0,d1), f(d2,d3)}, c1 = {g, o} ----
        float c0[4] = {0.f, 0.f, 0.f, 0.f};
        float c1[4] = {0.f, 0.f, 0.f, 0.f};

        #pragma unroll
        for (int ks = 0; ks < 8; ks++) {
            unsigned b0r, b1r;
            asm volatile("ldmatrix.sync.aligned.m8n8.x2.shared.b16 {%0,%1}, [%2];"
                : "=r"(b0r), "=r"(b1r) : "r"(lm + ks * 32));
            asm volatile(
                "mma.sync.aligned.m16n8k16.row.col.f32.f16.f16.f32 "
                "{%0,%1,%2,%3}, {%4,%5,%6,%7}, {%8,%9}, {%0,%1,%2,%3};"
                : "+f"(c0[0]), "+f"(c0[1]), "+f"(c0[2]), "+f"(c0[3])
                : "r"(Af[ks][0][0]), "r"(Af[ks][0][1]), "r"(Af[ks][0][2]), "r"(Af[ks][0][3]),
                  "r"(b0r), "r"(b1r));
            asm volatile(
                "mma.sync.aligned.m16n8k16.row.col.f32.f16.f16.f32 "
                "{%0,%1,%2,%3}, {%4,%5,%6,%7}, {%8,%9}, {%0,%1,%2,%3};"
                : "+f"(c1[0]), "+f"(c1[1]), "+f"(c1[2]), "+f"(c1[3])
                : "r"(Af[ks][1][0]), "r"(Af[ks][1][1]), "r"(Af[ks][1][2]), "r"(Af[ks][1][3]),
                  "r"(b0r), "r"(b1r));
        }

        // ---- in-register LSTM cell: 2 cells (batch brow0, brow1) at col hc ----
        // gx for i,f,o is pre-scaled by 0.5 (sigm(x) = 0.5*tanh(0.5x)+0.5)
        float ii0 = fmaf(tanhap(fmaf(c0[0], 0.5f, xi0)), 0.5f, 0.5f);
        float ii1 = fmaf(tanhap(fmaf(c0[1], 0.5f, xi1)), 0.5f, 0.5f);
        float ff0 = fmaf(tanhap(fmaf(c0[2], 0.5f, xf0)), 0.5f, 0.5f);
        float ff1 = fmaf(tanhap(fmaf(c0[3], 0.5f, xf1)), 0.5f, 0.5f);
        float gg0 = tanhap(c1[0] + xg0);
        float gg1 = tanhap(c1[1] + xg1);
        float oo0 = fmaf(tanhap(fmaf(c1[2], 0.5f, xo0)), 0.5f, 0.5f);
        float oo1 = fmaf(tanhap(fmaf(c1[3], 0.5f, xo1)), 0.5f, 0.5f);

        cst0 = fmaf(ff0, cst0, ii0 * gg0);
        cst1 = fmaf(ff1, cst1, ii1 * gg1);
        h0 = oo0 * tanhap(cst0);
        h1 = oo1 * tanhap(cst1);

        __half hh0 = __float2half(h0);
        __half hh1 = __float2half(h1);
        hw[(2 * tg)     * HAS_ + hc] = hh0;
        hw[(2 * tg + 1) * HAS_ + hc] = hh1;

        if (layer) {
            y1[((size_t)brow0 * T_ + t) * (2 * H_) + dir * H_ + hc] = h0;
            y1[((size_t)brow1 * T_ + t) * (2 * H_) + dir * H_ + hc] = h1;
        } else {
            g_y0h[((size_t)t * B_ + brow0) * (2 * H_) + dir * H_ + hc] = hh0;
            g_y0h[((size_t)t * B_ + brow1) * (2 * H_) + dir * H_ + hc] = hh1;
        }

        xi0 = ni0; xi1 = ni1; xf0 = nf0; xf1 = nf1;
        xg0 = ng0; xg1 = ng1; xo0 = no0; xo1 = no1;
        __syncthreads();   // step-s h writes visible before step-s+1 ldmatrix
    }

    const int d = layer * 2 + dir;
    hn[((size_t)d * B_ + brow0) * H_ + hc] = h0;
    hn[((size_t)d * B_ + brow1) * H_ + hc] = h1;
    cn[((size_t)d * B_ + brow0) * H_ + hc] = cst0;
    cn[((size_t)d * B_ + brow1) * H_ + hc] = cst1;
}

// ---------------- launch ----------------
extern "C" void kernel_launch(void* const* d_in, const int* in_sizes, int n_in,
                              void* d_out, int out_size) {
    const float* x     = (const float*)d_in[0];
    const float* wih0f = (const float*)d_in[1];
    const float* whh0f = (const float*)d_in[2];
    const float* b0f   = (const float*)d_in[3];
    const float* wih0b = (const float*)d_in[4];
    const float* whh0b = (const float*)d_in[5];
    const float* b0b   = (const float*)d_in[6];
    const float* wih1f = (const float*)d_in[7];
    const float* whh1f = (const float*)d_in[8];
    const float* b1f   = (const float*)d_in[9];
    const float* wih1b = (const float*)d_in[10];
    const float* whh1b = (const float*)d_in[11];
    const float* b1b   = (const float*)d_in[12];
    (void)in_sizes; (void)n_in; (void)out_size;

    float* out = (float*)d_out;
    float* y1 = out;
    float* hn = out + Y1SZ_;
    float* cn = hn + 4 * B_ * H_;

    // fp16 conversions
    conv_x_kernel<<<(BT_ * 32 + 255) / 256, 256>>>(x);
    conv_w_kernel<<<(2 * G_ * 32 + 2 * G_ * 256 + 255) / 256, 256>>>(wih0f, wih0b, wih1f, wih1b);

    // layer 0
    gemm_gx_kernel<<<dim3(BT_ / 128, G_ / 128, 2), 256>>>(b0f, b0b, 32);
    lstm_scan_mma<<<dim3(B_ / MB_, 2), 512>>>(whh0f, whh0b, y1, hn, cn, 0);

    // layer 1
    gemm_gx_kernel<<<dim3(BT_ / 128, G_ / 128, 2), 256>>>(b1f, b1b, 256);
    lstm_scan_mma<<<dim3(B_ / MB_, 2), 512>>>(whh1f, whh1b, y1, hn, cn, 1);
}

// round 9
// speedup vs baseline: 1.7912x; 1.2144x over previous
#include <cuda_runtime.h>
#include <cuda_fp16.h>
#include <cstdint>

#define B_  256
#define T_  512
#define I_  24
#define H_  128
#define G_  512           // 4*H
#define BT_ (B_*T_)       // 131072
#define MB_ 8             // batch rows per scan block
#define HAS_ 136          // hA row stride in halves (128 + 8 pad)
#define SAS_ 40           // GEMM smem row stride in halves (32 + 8 pad)
#define XS_  40           // x smem row stride in halves

static const size_t Y1SZ_ = (size_t)BT_ * 2 * H_;   // 33,554,432

// ---------------- scratch (no cudaMalloc allowed) ----------------
// gx (layer-1 only now) fp32, pre-scaled by 0.5 for gates i,f,o. [t][b][j].
__device__ float  g_gx[2][(size_t)BT_ * G_];        // 2 x 256 MB
__device__ __half g_y0h[(size_t)BT_ * 2 * H_];      // 64 MB, rows r' = t*B + b
__device__ __half g_xh[(size_t)BT_ * 32];           // x padded 24->32, rows r' = t*B + b
__device__ __half g_w1h[2][G_ * 256];               // w_ih layer1, fp16

__device__ __forceinline__ float tanhap(float x) {
    float y; asm("tanh.approx.f32 %0, %1;" : "=f"(y) : "f"(x)); return y;
}
__device__ __forceinline__ void cp16(unsigned dst, const void* src) {
    asm volatile("cp.async.ca.shared.global [%0], [%1], 16;" :: "r"(dst), "l"(src));
}

// ---------------- conversion kernels ----------------
__global__ void conv_x_kernel(const float* __restrict__ x) {
    int idx = blockIdx.x * 256 + threadIdx.x;
    if (idx < BT_ * 32) {
        int r = idx >> 5, i = idx & 31;       // r' = t*256 + b
        int b = r & 255, t = r >> 8;
        g_xh[idx] = (i < I_) ? __float2half(x[((size_t)b * T_ + t) * I_ + i]) : __float2half(0.f);
    }
}

__global__ void conv_w1_kernel(const float* __restrict__ w1f, const float* __restrict__ w1b) {
    int idx = blockIdx.x * 256 + threadIdx.x;
    if (idx < 2 * G_ * 256) {
        int d = idx / (G_ * 256); int p = idx % (G_ * 256);
        const float* w = d ? w1b : w1f;
        g_w1h[d][p] = __float2half(w[p]);
    }
}

// ---------------- pipelined input GEMM (layer 1; R6 verbatim, verified) ----------------
__global__ __launch_bounds__(256) void gemm_gx_kernel(
    const float* __restrict__ biasf, const float* __restrict__ biasb, int K)
{
    __shared__ __half sA[2][128 * SAS_];
    __shared__ __half sW[2][128 * SAS_];

    const int dir = blockIdx.z;
    const __half* __restrict__ A = g_y0h;
    const __half* __restrict__ W = g_w1h[dir];
    const float* __restrict__ bias = dir ? biasb : biasf;
    float* __restrict__ gx = g_gx[dir];

    const int tid  = threadIdx.x;
    const int lane = tid & 31;
    const int warp = tid >> 5;
    const int warpM = warp & 3;
    const int warpN = warp >> 2;
    const int g4 = lane >> 2;
    const int tg = lane & 3;
    const int mblk = blockIdx.x * 128;
    const int nblk = blockIdx.y * 128;
    const int nk = K >> 5;

    const unsigned sA_base = (unsigned)__cvta_generic_to_shared(sA);
    const unsigned sW_base = (unsigned)__cvta_generic_to_shared(sW);

    const int lrow = tid >> 2;
    const int lseg = tid & 3;

    auto load_stage = [&](int ks, int buf) {
        #pragma unroll
        for (int rr = 0; rr < 2; rr++) {
            int r = lrow + rr * 64;
            const __half* srcA = A + (size_t)(mblk + r) * K + ks * 32 + lseg * 8;
            const __half* srcW = W + (size_t)(nblk + r) * K + ks * 32 + lseg * 8;
            unsigned off = (unsigned)(buf * 128 * SAS_ + r * SAS_ + lseg * 8) * 2;
            cp16(sA_base + off, srcA);
            cp16(sW_base + off, srcW);
        }
        asm volatile("cp.async.commit_group;");
    };

    float acc[2][8][4];
    #pragma unroll
    for (int mf = 0; mf < 2; mf++)
        #pragma unroll
        for (int nf = 0; nf < 8; nf++)
            #pragma unroll
            for (int q = 0; q < 4; q++) acc[mf][nf][q] = 0.f;

    load_stage(0, 0);

    const unsigned lmA0 = sA_base + ((warpM * 32 + (lane & 15)) * SAS_ + (lane >> 4) * 8) * 2;
    const unsigned lmW0 = sW_base + ((warpN * 64 + (lane & 7)) * SAS_ + ((lane >> 3) & 1) * 8) * 2;

    for (int ks = 0; ks < nk; ks++) {
        const int buf = ks & 1;
        if (ks + 1 < nk) {
            load_stage(ks + 1, buf ^ 1);
            asm volatile("cp.async.wait_group 1;");
        } else {
            asm volatile("cp.async.wait_group 0;");
        }
        __syncthreads();

        const unsigned aBuf = lmA0 + buf * 128 * SAS_ * 2;
        const unsigned wBuf = lmW0 + buf * 128 * SAS_ * 2;

        #pragma unroll
        for (int kk = 0; kk < 2; kk++) {
            unsigned a[2][4];
            #pragma unroll
            for (int mf = 0; mf < 2; mf++) {
                asm volatile("ldmatrix.sync.aligned.m8n8.x4.shared.b16 {%0,%1,%2,%3}, [%4];"
                    : "=r"(a[mf][0]), "=r"(a[mf][1]), "=r"(a[mf][2]), "=r"(a[mf][3])
                    : "r"(aBuf + (mf * 16 * SAS_ + kk * 16) * 2));
            }
            #pragma unroll
            for (int nf = 0; nf < 8; nf++) {
                unsigned b0, b1;
                asm volatile("ldmatrix.sync.aligned.m8n8.x2.shared.b16 {%0,%1}, [%2];"
                    : "=r"(b0), "=r"(b1)
                    : "r"(wBuf + (nf * 8 * SAS_ + kk * 16) * 2));
                #pragma unroll
                for (int mf = 0; mf < 2; mf++) {
                    asm volatile(
                        "mma.sync.aligned.m16n8k16.row.col.f32.f16.f16.f32 "
                        "{%0,%1,%2,%3}, {%4,%5,%6,%7}, {%8,%9}, {%0,%1,%2,%3};"
                        : "+f"(acc[mf][nf][0]), "+f"(acc[mf][nf][1]),
                          "+f"(acc[mf][nf][2]), "+f"(acc[mf][nf][3])
                        : "r"(a[mf][0]), "r"(a[mf][1]), "r"(a[mf][2]), "r"(a[mf][3]),
                          "r"(b0), "r"(b1));
                }
            }
        }
        __syncthreads();
    }

    const int t = mblk >> 8;
    #pragma unroll
    for (int mf = 0; mf < 2; mf++) {
        int m = warpM * 32 + mf * 16 + g4;
        int b = (mblk & 255) + m;
        #pragma unroll
        for (int nf = 0; nf < 8; nf++) {
            int n0 = nblk + warpN * 64 + nf * 8 + tg * 2;
            float sc = ((n0 >> 7) == 2) ? 1.f : 0.5f;
            float bv0 = bias[n0], bv1 = bias[n0 + 1];
            *(float2*)&gx[((size_t)t * B_ + b)     * G_ + n0] =
                make_float2(sc * (acc[mf][nf][0] + bv0), sc * (acc[mf][nf][1] + bv1));
            *(float2*)&gx[((size_t)t * B_ + b + 8) * G_ + n0] =
                make_float2(sc * (acc[mf][nf][2] + bv0), sc * (acc[mf][nf][3] + bv1));
        }
    }
}

// ---------------- layer-0 FUSED scan: input GEMM folded into the recurrence ----
// Same transposed MMA structure as lstm_scan_mma, plus per step:
//  gates += Wih_perm @ x_t^T (2 k-steps), x_t[8,32] staged by one cp.async
//  warp-instr, double-buffered. Bias preloaded into accumulator init; 0.5
//  sigmoid prescale folded into Wih/Whh fragments and bias (g rows unscaled).
__global__ __launch_bounds__(512) void lstm_scan_fused0(
    const float* __restrict__ wihf, const float* __restrict__ whhf, const float* __restrict__ bf_,
    const float* __restrict__ wihb, const float* __restrict__ whhb, const float* __restrict__ bb_,
    float* __restrict__ hn, float* __restrict__ cn)
{
    __shared__ __half hA[2 * 8 * HAS_];   // h state, double-buffered
    __shared__ __half xS[2 * 8 * XS_];    // x_t staging, double-buffered

    const int tid  = threadIdx.x;
    const int lane = tid & 31;
    const int w    = tid >> 5;
    const int dir  = blockIdx.y;
    const int b0   = blockIdx.x * MB_;
    const int g4 = lane >> 2, tg = lane & 3;
    const float* __restrict__ whh  = dir ? whhb : whhf;
    const float* __restrict__ wih  = dir ? wihb : wihf;
    const float* __restrict__ bias = dir ? bb_ : bf_;

    // W_hh fragments, permuted tiles {i,f} / {g,o}, 0.5 folded into i,f,o rows
    unsigned Af[8][2][4];
    #pragma unroll
    for (int ks = 0; ks < 8; ks++)
        #pragma unroll
        for (int tl = 0; tl < 2; tl++) {
            const float* pA = whh + (size_t)((2 * tl)     * 128 + 8 * w + g4) * H_ + ks * 16 + tg * 2;
            const float* pB = whh + (size_t)((2 * tl + 1) * 128 + 8 * w + g4) * H_ + ks * 16 + tg * 2;
            float scA = (tl == 0) ? 0.5f : 1.0f;   // i:0.5, g:1.0
            float scB = 0.5f;                      // f, o
            float2 vA0 = *(const float2*)pA;
            float2 vB0 = *(const float2*)pB;
            float2 vA1 = *(const float2*)(pA + 8);
            float2 vB1 = *(const float2*)(pB + 8);
            __half2 h0 = __floats2half2_rn(scA * vA0.x, scA * vA0.y);
            __half2 h1 = __floats2half2_rn(scB * vB0.x, scB * vB0.y);
            __half2 h2 = __floats2half2_rn(scA * vA1.x, scA * vA1.y);
            __half2 h3 = __floats2half2_rn(scB * vB1.x, scB * vB1.y);
            Af[ks][tl][0] = *(unsigned*)&h0;
            Af[ks][tl][1] = *(unsigned*)&h1;
            Af[ks][tl][2] = *(unsigned*)&h2;
            Af[ks][tl][3] = *(unsigned*)&h3;
        }

    // W_ih fragments (K=32, cols >= 24 zero), same permutation + scaling
    unsigned Ax[2][2][4];
    #pragma unroll
    for (int ks = 0; ks < 2; ks++)
        #pragma unroll
        for (int tl = 0; tl < 2; tl++) {
            int rA = (2 * tl) * 128 + 8 * w + g4;
            int rB = (2 * tl + 1) * 128 + 8 * w + g4;
            float scA = (tl == 0) ? 0.5f : 1.0f;
            float scB = 0.5f;
            int k0 = ks * 16 + tg * 2;      // <= 22
            int k1 = k0 + 8;                // may exceed 23
            float2 vA0 = *(const float2*)(wih + (size_t)rA * I_ + k0);
            float2 vB0 = *(const float2*)(wih + (size_t)rB * I_ + k0);
            float2 vA1 = (k1 < I_) ? *(const float2*)(wih + (size_t)rA * I_ + k1) : make_float2(0.f, 0.f);
            float2 vB1 = (k1 < I_) ? *(const float2*)(wih + (size_t)rB * I_ + k1) : make_float2(0.f, 0.f);
            __half2 h0 = __floats2half2_rn(scA * vA0.x, scA * vA0.y);
            __half2 h1 = __floats2half2_rn(scB * vB0.x, scB * vB0.y);
            __half2 h2 = __floats2half2_rn(scA * vA1.x, scA * vA1.y);
            __half2 h3 = __floats2half2_rn(scB * vB1.x, scB * vB1.y);
            Ax[ks][tl][0] = *(unsigned*)&h0;
            Ax[ks][tl][1] = *(unsigned*)&h1;
            Ax[ks][tl][2] = *(unsigned*)&h2;
            Ax[ks][tl][3] = *(unsigned*)&h3;
        }

    const int hc = 8 * w + g4;
    // bias accumulator-init values (0.5 folded for i,f,o)
    const float bi = 0.5f * bias[hc];
    const float bfv = 0.5f * bias[128 + hc];
    const float bg  = bias[256 + hc];
    const float bo  = 0.5f * bias[384 + hc];

    for (int p = tid; p < 2 * 8 * HAS_; p += 512) hA[p] = __float2half(0.f);

    const int brow0 = b0 + 2 * tg;
    const int brow1 = brow0 + 1;
    float cst0 = 0.f, cst1 = 0.f;
    float h0v = 0.f, h1v = 0.f;

    const unsigned hA_base = (unsigned)__cvta_generic_to_shared(hA);
    const unsigned xS_base = (unsigned)__cvta_generic_to_shared(xS);
    const unsigned lmB  = hA_base + (((lane & 7) * HAS_) + (((lane >> 3) & 1) * 8)) * 2;
    const unsigned lmX  = xS_base + (((lane & 7) * XS_) + (((lane >> 3) & 1) * 8)) * 2;
    const unsigned BUFB = 8 * HAS_ * 2;
    const unsigned XBUF = 8 * XS_ * 2;

    // preload x for first step into buf 0
    {
        int t0 = dir ? (T_ - 1) : 0;
        if (tid < 32) {
            int row = tid >> 2, seg = tid & 3;
            cp16(xS_base + (unsigned)(row * XS_ + seg * 8) * 2,
                 g_xh + ((size_t)t0 * B_ + b0 + row) * 32 + seg * 8);
            asm volatile("cp.async.commit_group;");
            asm volatile("cp.async.wait_group 0;");
        }
    }
    __syncthreads();

    for (int s = 0; s < T_; s++) {
        const int t = dir ? (T_ - 1 - s) : s;
        const int rb = s & 1;
        const unsigned lm = lmB + rb * BUFB;
        const unsigned lx = lmX + rb * XBUF;
        __half* hw = hA + (rb ^ 1) * 8 * HAS_;

        // kick cp.async for next step's x into the other buffer
        if (s + 1 < T_ && tid < 32) {
            int tn = dir ? (T_ - 2 - s) : (s + 1);
            int row = tid >> 2, seg = tid & 3;
            cp16(xS_base + (rb ^ 1) * XBUF + (unsigned)(row * XS_ + seg * 8) * 2,
                 g_xh + ((size_t)tn * B_ + b0 + row) * 32 + seg * 8);
            asm volatile("cp.async.commit_group;");
        }

        // accumulators init = bias
        float c0[4] = {bi, bi, bfv, bfv};
        float c1[4] = {bg, bg, bo, bo};

        // x contribution: 2 k-steps
        #pragma unroll
        for (int ks = 0; ks < 2; ks++) {
            unsigned b0r, b1r;
            asm volatile("ldmatrix.sync.aligned.m8n8.x2.shared.b16 {%0,%1}, [%2];"
                : "=r"(b0r), "=r"(b1r) : "r"(lx + ks * 32));
            asm volatile(
                "mma.sync.aligned.m16n8k16.row.col.f32.f16.f16.f32 "
                "{%0,%1,%2,%3}, {%4,%5,%6,%7}, {%8,%9}, {%0,%1,%2,%3};"
                : "+f"(c0[0]), "+f"(c0[1]), "+f"(c0[2]), "+f"(c0[3])
                : "r"(Ax[ks][0][0]), "r"(Ax[ks][0][1]), "r"(Ax[ks][0][2]), "r"(Ax[ks][0][3]),
                  "r"(b0r), "r"(b1r));
            asm volatile(
                "mma.sync.aligned.m16n8k16.row.col.f32.f16.f16.f32 "
                "{%0,%1,%2,%3}, {%4,%5,%6,%7}, {%8,%9}, {%0,%1,%2,%3};"
                : "+f"(c1[0]), "+f"(c1[1]), "+f"(c1[2]), "+f"(c1[3])
                : "r"(Ax[ks][1][0]), "r"(Ax[ks][1][1]), "r"(Ax[ks][1][2]), "r"(Ax[ks][1][3]),
                  "r"(b0r), "r"(b1r));
        }

        // h contribution: 8 k-steps
        #pragma unroll
        for (int ks = 0; ks < 8; ks++) {
            unsigned b0r, b1r;
            asm volatile("ldmatrix.sync.aligned.m8n8.x2.shared.b16 {%0,%1}, [%2];"
                : "=r"(b0r), "=r"(b1r) : "r"(lm + ks * 32));
            asm volatile(
                "mma.sync.aligned.m16n8k16.row.col.f32.f16.f16.f32 "
                "{%0,%1,%2,%3}, {%4,%5,%6,%7}, {%8,%9}, {%0,%1,%2,%3};"
                : "+f"(c0[0]), "+f"(c0[1]), "+f"(c0[2]), "+f"(c0[3])
                : "r"(Af[ks][0][0]), "r"(Af[ks][0][1]), "r"(Af[ks][0][2]), "r"(Af[ks][0][3]),
                  "r"(b0r), "r"(b1r));
            asm volatile(
                "mma.sync.aligned.m16n8k16.row.col.f32.f16.f16.f32 "
                "{%0,%1,%2,%3}, {%4,%5,%6,%7}, {%8,%9}, {%0,%1,%2,%3};"
                : "+f"(c1[0]), "+f"(c1[1]), "+f"(c1[2]), "+f"(c1[3])
                : "r"(Af[ks][1][0]), "r"(Af[ks][1][1]), "r"(Af[ks][1][2]), "r"(Af[ks][1][3]),
                  "r"(b0r), "r"(b1r));
        }

        // in-register LSTM cell (everything prescaled; accumulator holds full gate)
        float ii0 = fmaf(tanhap(c0[0]), 0.5f, 0.5f);
        float ii1 = fmaf(tanhap(c0[1]), 0.5f, 0.5f);
        float ff0 = fmaf(tanhap(c0[2]), 0.5f, 0.5f);
        float ff1 = fmaf(tanhap(c0[3]), 0.5f, 0.5f);
        float gg0 = tanhap(c1[0]);
        float gg1 = tanhap(c1[1]);
        float oo0 = fmaf(tanhap(c1[2]), 0.5f, 0.5f);
        float oo1 = fmaf(tanhap(c1[3]), 0.5f, 0.5f);

        cst0 = fmaf(ff0, cst0, ii0 * gg0);
        cst1 = fmaf(ff1, cst1, ii1 * gg1);
        h0v = oo0 * tanhap(cst0);
        h1v = oo1 * tanhap(cst1);

        __half hh0 = __float2half(h0v);
        __half hh1 = __float2half(h1v);
        hw[(2 * tg)     * HAS_ + hc] = hh0;
        hw[(2 * tg + 1) * HAS_ + hc] = hh1;

        g_y0h[((size_t)t * B_ + brow0) * (2 * H_) + dir * H_ + hc] = hh0;
        g_y0h[((size_t)t * B_ + brow1) * (2 * H_) + dir * H_ + hc] = hh1;

        if (s + 1 < T_ && tid < 32) {
            asm volatile("cp.async.wait_group 0;");
        }
        __syncthreads();
    }

    const int d = dir;   // layer 0
    hn[((size_t)d * B_ + brow0) * H_ + hc] = h0v;
    hn[((size_t)d * B_ + brow1) * H_ + hc] = h1v;
    cn[((size_t)d * B_ + brow0) * H_ + hc] = cst0;
    cn[((size_t)d * B_ + brow1) * H_ + hc] = cst1;
}

// ---------------- layer-1 transposed scan (R8 verbatim, verified) ----------------
__global__ __launch_bounds__(512) void lstm_scan_mma(
    const float* __restrict__ whhf, const float* __restrict__ whhb,
    float* __restrict__ y1, float* __restrict__ hn, float* __restrict__ cn, int layer)
{
    __shared__ __half hA[2 * 8 * HAS_];

    const int tid  = threadIdx.x;
    const int lane = tid & 31;
    const int w    = tid >> 5;
    const int dir  = blockIdx.y;
    const int b0   = blockIdx.x * MB_;
    const int g4 = lane >> 2, tg = lane & 3;
    const float* __restrict__ whh = dir ? whhb : whhf;
    const float* __restrict__ gx  = g_gx[dir];

    unsigned Af[8][2][4];
    #pragma unroll
    for (int ks = 0; ks < 8; ks++)
        #pragma unroll
        for (int tl = 0; tl < 2; tl++) {
            const float* pA = whh + (size_t)((2 * tl)     * 128 + 8 * w + g4) * H_ + ks * 16 + tg * 2;
            const float* pB = whh + (size_t)((2 * tl + 1) * 128 + 8 * w + g4) * H_ + ks * 16 + tg * 2;
            float2 vA0 = *(const float2*)pA;
            float2 vB0 = *(const float2*)pB;
            float2 vA1 = *(const float2*)(pA + 8);
            float2 vB1 = *(const float2*)(pB + 8);
            __half2 h0 = __floats2half2_rn(vA0.x, vA0.y);
            __half2 h1 = __floats2half2_rn(vB0.x, vB0.y);
            __half2 h2 = __floats2half2_rn(vA1.x, vA1.y);
            __half2 h3 = __floats2half2_rn(vB1.x, vB1.y);
            Af[ks][tl][0] = *(unsigned*)&h0;
            Af[ks][tl][1] = *(unsigned*)&h1;
            Af[ks][tl][2] = *(unsigned*)&h2;
            Af[ks][tl][3] = *(unsigned*)&h3;
        }

    for (int p = tid; p < 2 * 8 * HAS_; p += 512) hA[p] = __float2half(0.f);

    const int hc    = 8 * w + g4;
    const int brow0 = b0 + 2 * tg;
    const int brow1 = brow0 + 1;
    float cst0 = 0.f, cst1 = 0.f;
    float h0 = 0.f, h1 = 0.f;

    const unsigned hA_base = (unsigned)__cvta_generic_to_shared(hA);
    const unsigned lmB = hA_base + (((lane & 7) * HAS_) + (((lane >> 3) & 1) * 8)) * 2;
    const unsigned BUFB = 8 * HAS_ * 2;

    __syncthreads();

    float xi0, xi1, xf0, xf1, xg0, xg1, xo0, xo1;
    {
        int t0 = dir ? (T_ - 1) : 0;
        const float* p0 = gx + ((size_t)t0 * B_ + brow0) * G_ + hc;
        const float* p1 = gx + ((size_t)t0 * B_ + brow1) * G_ + hc;
        xi0 = p0[0];   xi1 = p1[0];
        xf0 = p0[128]; xf1 = p1[128];
        xg0 = p0[256]; xg1 = p1[256];
        xo0 = p0[384]; xo1 = p1[384];
    }

    for (int s = 0; s < T_; s++) {
        const int t = dir ? (T_ - 1 - s) : s;
        const int rb = s & 1;
        const unsigned lm = lmB + rb * BUFB;
        __half* hw = hA + (rb ^ 1) * 8 * HAS_;

        float ni0, ni1, nf0, nf1, ng0, ng1, no0, no1;
        if (s + 1 < T_) {
            int tn = dir ? (T_ - 2 - s) : (s + 1);
            const float* p0 = gx + ((size_t)tn * B_ + brow0) * G_ + hc;
            const float* p1 = gx + ((size_t)tn * B_ + brow1) * G_ + hc;
            ni0 = p0[0];   ni1 = p1[0];
            nf0 = p0[128]; nf1 = p1[128];
            ng0 = p0[256]; ng1 = p1[256];
            no0 = p0[384]; no1 = p1[384];
        } else {
            ni0 = ni1 = nf0 = nf1 = ng0 = ng1 = no0 = no1 = 0.f;
        }

        float c0[4] = {0.f, 0.f, 0.f, 0.f};
        float c1[4] = {0.f, 0.f, 0.f, 0.f};

        #pragma unroll
        for (int ks = 0; ks < 8; ks++) {
            unsigned b0r, b1r;
            asm volatile("ldmatrix.sync.aligned.m8n8.x2.shared.b16 {%0,%1}, [%2];"
                : "=r"(b0r), "=r"(b1r) : "r"(lm + ks * 32));
            asm volatile(
                "mma.sync.aligned.m16n8k16.row.col.f32.f16.f16.f32 "
                "{%0,%1,%2,%3}, {%4,%5,%6,%7}, {%8,%9}, {%0,%1,%2,%3};"
                : "+f"(c0[0]), "+f"(c0[1]), "+f"(c0[2]), "+f"(c0[3])
                : "r"(Af[ks][0][0]), "r"(Af[ks][0][1]), "r"(Af[ks][0][2]), "r"(Af[ks][0][3]),
                  "r"(b0r), "r"(b1r));
            asm volatile(
                "mma.sync.aligned.m16n8k16.row.col.f32.f16.f16.f32 "
                "{%0,%1,%2,%3}, {%4,%5,%6,%7}, {%8,%9}, {%0,%1,%2,%3};"
                : "+f"(c1[0]), "+f"(c1[1]), "+f"(c1[2]), "+f"(c1[3])
                : "r"(Af[ks][1][0]), "r"(Af[ks][1][1]), "r"(Af[ks][1][2]), "r"(Af[ks][1][3]),
                  "r"(b0r), "r"(b1r));
        }

        float ii0 = fmaf(tanhap(fmaf(c0[0], 0.5f, xi0)), 0.5f, 0.5f);
        float ii1 = fmaf(tanhap(fmaf(c0[1], 0.5f, xi1)), 0.5f, 0.5f);
        float ff0 = fmaf(tanhap(fmaf(c0[2], 0.5f, xf0)), 0.5f, 0.5f);
        float ff1 = fmaf(tanhap(fmaf(c0[3], 0.5f, xf1)), 0.5f, 0.5f);
        float gg0 = tanhap(c1[0] + xg0);
        float gg1 = tanhap(c1[1] + xg1);
        float oo0 = fmaf(tanhap(fmaf(c1[2], 0.5f, xo0)), 0.5f, 0.5f);
        float oo1 = fmaf(tanhap(fmaf(c1[3], 0.5f, xo1)), 0.5f, 0.5f);

        cst0 = fmaf(ff0, cst0, ii0 * gg0);
        cst1 = fmaf(ff1, cst1, ii1 * gg1);
        h0 = oo0 * tanhap(cst0);
        h1 = oo1 * tanhap(cst1);

        __half hh0 = __float2half(h0);
        __half hh1 = __float2half(h1);
        hw[(2 * tg)     * HAS_ + hc] = hh0;
        hw[(2 * tg + 1) * HAS_ + hc] = hh1;

        if (layer) {
            y1[((size_t)brow0 * T_ + t) * (2 * H_) + dir * H_ + hc] = h0;
            y1[((size_t)brow1 * T_ + t) * (2 * H_) + dir * H_ + hc] = h1;
        } else {
            g_y0h[((size_t)t * B_ + brow0) * (2 * H_) + dir * H_ + hc] = hh0;
            g_y0h[((size_t)t * B_ + brow1) * (2 * H_) + dir * H_ + hc] = hh1;
        }

        xi0 = ni0; xi1 = ni1; xf0 = nf0; xf1 = nf1;
        xg0 = ng0; xg1 = ng1; xo0 = no0; xo1 = no1;
        __syncthreads();
    }

    const int d = layer * 2 + dir;
    hn[((size_t)d * B_ + brow0) * H_ + hc] = h0;
    hn[((size_t)d * B_ + brow1) * H_ + hc] = h1;
    cn[((size_t)d * B_ + brow0) * H_ + hc] = cst0;
    cn[((size_t)d * B_ + brow1) * H_ + hc] = cst1;
}

// ---------------- launch ----------------
extern "C" void kernel_launch(void* const* d_in, const int* in_sizes, int n_in,
                              void* d_out, int out_size) {
    const float* x     = (const float*)d_in[0];
    const float* wih0f = (const float*)d_in[1];
    const float* whh0f = (const float*)d_in[2];
    const float* b0f   = (const float*)d_in[3];
    const float* wih0b = (const float*)d_in[4];
    const float* whh0b = (const float*)d_in[5];
    const float* b0b   = (const float*)d_in[6];
    const float* wih1f = (const float*)d_in[7];
    const float* whh1f = (const float*)d_in[8];
    const float* b1f   = (const float*)d_in[9];
    const float* wih1b = (const float*)d_in[10];
    const float* whh1b = (const float*)d_in[11];
    const float* b1b   = (const float*)d_in[12];
    (void)in_sizes; (void)n_in; (void)out_size;

    float* out = (float*)d_out;
    float* y1 = out;
    float* hn = out + Y1SZ_;
    float* cn = hn + 4 * B_ * H_;

    // fp16 conversions
    conv_x_kernel<<<(BT_ * 32 + 255) / 256, 256>>>(x);
    conv_w1_kernel<<<(2 * G_ * 256 + 255) / 256, 256>>>(wih1f, wih1b);

    // layer 0: fused input-GEMM + scan (no gx materialization)
    lstm_scan_fused0<<<dim3(B_ / MB_, 2), 512>>>(wih0f, whh0f, b0f, wih0b, whh0b, b0b, hn, cn);

    // layer 1
    gemm_gx_kernel<<<dim3(BT_ / 128, G_ / 128, 2), 256>>>(b1f, b1b, 256);
    lstm_scan_mma<<<dim3(B_ / MB_, 2), 512>>>(whh1f, whh1b, y1, hn, cn, 1);
}

// round 10
// speedup vs baseline: 1.8469x; 1.0311x over previous
#include <cuda_runtime.h>
#include <cuda_fp16.h>
#include <cstdint>

#define B_  256
#define T_  512
#define I_  24
#define H_  128
#define G_  512           // 4*H
#define BT_ (B_*T_)       // 131072
#define MB_ 8             // batch rows per scan block
#define HAS_ 136          // hA row stride in halves (128 + 8 pad)
#define SAS_ 40           // GEMM smem row stride in halves (32 + 8 pad)
#define XS_  40           // x smem row stride in halves
#define GSP_ 516          // gx smem row stride in floats (512 + 4 pad)

static const size_t Y1SZ_ = (size_t)BT_ * 2 * H_;   // 33,554,432

// ---------------- scratch (no cudaMalloc allowed) ----------------
__device__ float  g_gx[2][(size_t)BT_ * G_];        // layer-1 gx, fp32, [t][b][j]
__device__ __half g_y0h[(size_t)BT_ * 2 * H_];      // 64 MB, rows r' = t*B + b
__device__ __half g_xh[(size_t)BT_ * 32];           // x padded 24->32, rows r' = t*B + b
__device__ __half g_w1h[2][G_ * 256];               // w_ih layer1, fp16

__device__ __forceinline__ float tanhap(float x) {
    float y; asm("tanh.approx.f32 %0, %1;" : "=f"(y) : "f"(x)); return y;
}
__device__ __forceinline__ void cp16(unsigned dst, const void* src) {
    asm volatile("cp.async.ca.shared.global [%0], [%1], 16;" :: "r"(dst), "l"(src));
}

// ---------------- conversion kernels ----------------
__global__ void conv_x_kernel(const float* __restrict__ x) {
    int idx = blockIdx.x * 256 + threadIdx.x;
    if (idx < BT_ * 32) {
        int r = idx >> 5, i = idx & 31;       // r' = t*256 + b
        int b = r & 255, t = r >> 8;
        g_xh[idx] = (i < I_) ? __float2half(x[((size_t)b * T_ + t) * I_ + i]) : __float2half(0.f);
    }
}

__global__ void conv_w1_kernel(const float* __restrict__ w1f, const float* __restrict__ w1b) {
    int idx = blockIdx.x * 256 + threadIdx.x;
    if (idx < 2 * G_ * 256) {
        int d = idx / (G_ * 256); int p = idx % (G_ * 256);
        const float* w = d ? w1b : w1f;
        g_w1h[d][p] = __float2half(w[p]);
    }
}

// ---------------- pipelined input GEMM (layer 1) ----------------
// Grid (8, BT/128): blockIdx.x = (dir<<2 | n-tile) fastest-varying so the 8
// blocks sharing one A M-tile run concurrently -> A read once from DRAM.
__global__ __launch_bounds__(256) void gemm_gx_kernel(
    const float* __restrict__ biasf, const float* __restrict__ biasb)
{
    const int K = 256;
    __shared__ __half sA[2][128 * SAS_];
    __shared__ __half sW[2][128 * SAS_];

    const int dir = blockIdx.x >> 2;
    const __half* __restrict__ A = g_y0h;
    const __half* __restrict__ W = g_w1h[dir];
    const float* __restrict__ bias = dir ? biasb : biasf;
    float* __restrict__ gx = g_gx[dir];

    const int tid  = threadIdx.x;
    const int lane = tid & 31;
    const int warp = tid >> 5;
    const int warpM = warp & 3;
    const int warpN = warp >> 2;
    const int g4 = lane >> 2;
    const int tg = lane & 3;
    const int mblk = blockIdx.y * 128;
    const int nblk = (blockIdx.x & 3) * 128;
    const int nk = K >> 5;

    const unsigned sA_base = (unsigned)__cvta_generic_to_shared(sA);
    const unsigned sW_base = (unsigned)__cvta_generic_to_shared(sW);

    const int lrow = tid >> 2;
    const int lseg = tid & 3;

    auto load_stage = [&](int ks, int buf) {
        #pragma unroll
        for (int rr = 0; rr < 2; rr++) {
            int r = lrow + rr * 64;
            const __half* srcA = A + (size_t)(mblk + r) * K + ks * 32 + lseg * 8;
            const __half* srcW = W + (size_t)(nblk + r) * K + ks * 32 + lseg * 8;
            unsigned off = (unsigned)(buf * 128 * SAS_ + r * SAS_ + lseg * 8) * 2;
            cp16(sA_base + off, srcA);
            cp16(sW_base + off, srcW);
        }
        asm volatile("cp.async.commit_group;");
    };

    float acc[2][8][4];
    #pragma unroll
    for (int mf = 0; mf < 2; mf++)
        #pragma unroll
        for (int nf = 0; nf < 8; nf++)
            #pragma unroll
            for (int q = 0; q < 4; q++) acc[mf][nf][q] = 0.f;

    load_stage(0, 0);

    const unsigned lmA0 = sA_base + ((warpM * 32 + (lane & 15)) * SAS_ + (lane >> 4) * 8) * 2;
    const unsigned lmW0 = sW_base + ((warpN * 64 + (lane & 7)) * SAS_ + ((lane >> 3) & 1) * 8) * 2;

    for (int ks = 0; ks < nk; ks++) {
        const int buf = ks & 1;
        if (ks + 1 < nk) {
            load_stage(ks + 1, buf ^ 1);
            asm volatile("cp.async.wait_group 1;");
        } else {
            asm volatile("cp.async.wait_group 0;");
        }
        __syncthreads();

        const unsigned aBuf = lmA0 + buf * 128 * SAS_ * 2;
        const unsigned wBuf = lmW0 + buf * 128 * SAS_ * 2;

        #pragma unroll
        for (int kk = 0; kk < 2; kk++) {
            unsigned a[2][4];
            #pragma unroll
            for (int mf = 0; mf < 2; mf++) {
                asm volatile("ldmatrix.sync.aligned.m8n8.x4.shared.b16 {%0,%1,%2,%3}, [%4];"
                    : "=r"(a[mf][0]), "=r"(a[mf][1]), "=r"(a[mf][2]), "=r"(a[mf][3])
                    : "r"(aBuf + (mf * 16 * SAS_ + kk * 16) * 2));
            }
            #pragma unroll
            for (int nf = 0; nf < 8; nf++) {
                unsigned b0, b1;
                asm volatile("ldmatrix.sync.aligned.m8n8.x2.shared.b16 {%0,%1}, [%2];"
                    : "=r"(b0), "=r"(b1)
                    : "r"(wBuf + (nf * 8 * SAS_ + kk * 16) * 2));
                #pragma unroll
                for (int mf = 0; mf < 2; mf++) {
                    asm volatile(
                        "mma.sync.aligned.m16n8k16.row.col.f32.f16.f16.f32 "
                        "{%0,%1,%2,%3}, {%4,%5,%6,%7}, {%8,%9}, {%0,%1,%2,%3};"
                        : "+f"(acc[mf][nf][0]), "+f"(acc[mf][nf][1]),
                          "+f"(acc[mf][nf][2]), "+f"(acc[mf][nf][3])
                        : "r"(a[mf][0]), "r"(a[mf][1]), "r"(a[mf][2]), "r"(a[mf][3]),
                          "r"(b0), "r"(b1));
                }
            }
        }
        __syncthreads();
    }

    const int t = mblk >> 8;
    #pragma unroll
    for (int mf = 0; mf < 2; mf++) {
        int m = warpM * 32 + mf * 16 + g4;
        int b = (mblk & 255) + m;
        #pragma unroll
        for (int nf = 0; nf < 8; nf++) {
            int n0 = nblk + warpN * 64 + nf * 8 + tg * 2;
            float sc = ((n0 >> 7) == 2) ? 1.f : 0.5f;
            float bv0 = bias[n0], bv1 = bias[n0 + 1];
            *(float2*)&gx[((size_t)t * B_ + b)     * G_ + n0] =
                make_float2(sc * (acc[mf][nf][0] + bv0), sc * (acc[mf][nf][1] + bv1));
            *(float2*)&gx[((size_t)t * B_ + b + 8) * G_ + n0] =
                make_float2(sc * (acc[mf][nf][2] + bv0), sc * (acc[mf][nf][3] + bv1));
        }
    }
}

// ---------------- layer-0 FUSED scan (R9 verbatim, verified) ----------------
__global__ __launch_bounds__(512) void lstm_scan_fused0(
    const float* __restrict__ wihf, const float* __restrict__ whhf, const float* __restrict__ bf_,
    const float* __restrict__ wihb, const float* __restrict__ whhb, const float* __restrict__ bb_,
    float* __restrict__ hn, float* __restrict__ cn)
{
    __shared__ __half hA[2 * 8 * HAS_];
    __shared__ __half xS[2 * 8 * XS_];

    const int tid  = threadIdx.x;
    const int lane = tid & 31;
    const int w    = tid >> 5;
    const int dir  = blockIdx.y;
    const int b0   = blockIdx.x * MB_;
    const int g4 = lane >> 2, tg = lane & 3;
    const float* __restrict__ whh  = dir ? whhb : whhf;
    const float* __restrict__ wih  = dir ? wihb : wihf;
    const float* __restrict__ bias = dir ? bb_ : bf_;

    unsigned Af[8][2][4];
    #pragma unroll
    for (int ks = 0; ks < 8; ks++)
        #pragma unroll
        for (int tl = 0; tl < 2; tl++) {
            const float* pA = whh + (size_t)((2 * tl)     * 128 + 8 * w + g4) * H_ + ks * 16 + tg * 2;
            const float* pB = whh + (size_t)((2 * tl + 1) * 128 + 8 * w + g4) * H_ + ks * 16 + tg * 2;
            float scA = (tl == 0) ? 0.5f : 1.0f;
            float scB = 0.5f;
            float2 vA0 = *(const float2*)pA;
            float2 vB0 = *(const float2*)pB;
            float2 vA1 = *(const float2*)(pA + 8);
            float2 vB1 = *(const float2*)(pB + 8);
            __half2 h0 = __floats2half2_rn(scA * vA0.x, scA * vA0.y);
            __half2 h1 = __floats2half2_rn(scB * vB0.x, scB * vB0.y);
            __half2 h2 = __floats2half2_rn(scA * vA1.x, scA * vA1.y);
            __half2 h3 = __floats2half2_rn(scB * vB1.x, scB * vB1.y);
            Af[ks][tl][0] = *(unsigned*)&h0;
            Af[ks][tl][1] = *(unsigned*)&h1;
            Af[ks][tl][2] = *(unsigned*)&h2;
            Af[ks][tl][3] = *(unsigned*)&h3;
        }

    unsigned Ax[2][2][4];
    #pragma unroll
    for (int ks = 0; ks < 2; ks++)
        #pragma unroll
        for (int tl = 0; tl < 2; tl++) {
            int rA = (2 * tl) * 128 + 8 * w + g4;
            int rB = (2 * tl + 1) * 128 + 8 * w + g4;
            float scA = (tl == 0) ? 0.5f : 1.0f;
            float scB = 0.5f;
            int k0 = ks * 16 + tg * 2;
            int k1 = k0 + 8;
            float2 vA0 = *(const float2*)(wih + (size_t)rA * I_ + k0);
            float2 vB0 = *(const float2*)(wih + (size_t)rB * I_ + k0);
            float2 vA1 = (k1 < I_) ? *(const float2*)(wih + (size_t)rA * I_ + k1) : make_float2(0.f, 0.f);
            float2 vB1 = (k1 < I_) ? *(const float2*)(wih + (size_t)rB * I_ + k1) : make_float2(0.f, 0.f);
            __half2 h0 = __floats2half2_rn(scA * vA0.x, scA * vA0.y);
            __half2 h1 = __floats2half2_rn(scB * vB0.x, scB * vB0.y);
            __half2 h2 = __floats2half2_rn(scA * vA1.x, scA * vA1.y);
            __half2 h3 = __floats2half2_rn(scB * vB1.x, scB * vB1.y);
            Ax[ks][tl][0] = *(unsigned*)&h0;
            Ax[ks][tl][1] = *(unsigned*)&h1;
            Ax[ks][tl][2] = *(unsigned*)&h2;
            Ax[ks][tl][3] = *(unsigned*)&h3;
        }

    const int hc = 8 * w + g4;
    const float bi = 0.5f * bias[hc];
    const float bfv = 0.5f * bias[128 + hc];
    const float bg  = bias[256 + hc];
    const float bo  = 0.5f * bias[384 + hc];

    for (int p = tid; p < 2 * 8 * HAS_; p += 512) hA[p] = __float2half(0.f);

    const int brow0 = b0 + 2 * tg;
    const int brow1 = brow0 + 1;
    float cst0 = 0.f, cst1 = 0.f;
    float h0v = 0.f, h1v = 0.f;

    const unsigned hA_base = (unsigned)__cvta_generic_to_shared(hA);
    const unsigned xS_base = (unsigned)__cvta_generic_to_shared(xS);
    const unsigned lmB  = hA_base + (((lane & 7) * HAS_) + (((lane >> 3) & 1) * 8)) * 2;
    const unsigned lmX  = xS_base + (((lane & 7) * XS_) + (((lane >> 3) & 1) * 8)) * 2;
    const unsigned BUFB = 8 * HAS_ * 2;
    const unsigned XBUF = 8 * XS_ * 2;

    {
        int t0 = dir ? (T_ - 1) : 0;
        if (tid < 32) {
            int row = tid >> 2, seg = tid & 3;
            cp16(xS_base + (unsigned)(row * XS_ + seg * 8) * 2,
                 g_xh + ((size_t)t0 * B_ + b0 + row) * 32 + seg * 8);
            asm volatile("cp.async.commit_group;");
            asm volatile("cp.async.wait_group 0;");
        }
    }
    __syncthreads();

    for (int s = 0; s < T_; s++) {
        const int t = dir ? (T_ - 1 - s) : s;
        const int rb = s & 1;
        const unsigned lm = lmB + rb * BUFB;
        const unsigned lx = lmX + rb * XBUF;
        __half* hw = hA + (rb ^ 1) * 8 * HAS_;

        if (s + 1 < T_ && tid < 32) {
            int tn = dir ? (T_ - 2 - s) : (s + 1);
            int row = tid >> 2, seg = tid & 3;
            cp16(xS_base + (rb ^ 1) * XBUF + (unsigned)(row * XS_ + seg * 8) * 2,
                 g_xh + ((size_t)tn * B_ + b0 + row) * 32 + seg * 8);
            asm volatile("cp.async.commit_group;");
        }

        float c0[4] = {bi, bi, bfv, bfv};
        float c1[4] = {bg, bg, bo, bo};

        #pragma unroll
        for (int ks = 0; ks < 2; ks++) {
            unsigned b0r, b1r;
            asm volatile("ldmatrix.sync.aligned.m8n8.x2.shared.b16 {%0,%1}, [%2];"
                : "=r"(b0r), "=r"(b1r) : "r"(lx + ks * 32));
            asm volatile(
                "mma.sync.aligned.m16n8k16.row.col.f32.f16.f16.f32 "
                "{%0,%1,%2,%3}, {%4,%5,%6,%7}, {%8,%9}, {%0,%1,%2,%3};"
                : "+f"(c0[0]), "+f"(c0[1]), "+f"(c0[2]), "+f"(c0[3])
                : "r"(Ax[ks][0][0]), "r"(Ax[ks][0][1]), "r"(Ax[ks][0][2]), "r"(Ax[ks][0][3]),
                  "r"(b0r), "r"(b1r));
            asm volatile(
                "mma.sync.aligned.m16n8k16.row.col.f32.f16.f16.f32 "
                "{%0,%1,%2,%3}, {%4,%5,%6,%7}, {%8,%9}, {%0,%1,%2,%3};"
                : "+f"(c1[0]), "+f"(c1[1]), "+f"(c1[2]), "+f"(c1[3])
                : "r"(Ax[ks][1][0]), "r"(Ax[ks][1][1]), "r"(Ax[ks][1][2]), "r"(Ax[ks][1][3]),
                  "r"(b0r), "r"(b1r));
        }

        #pragma unroll
        for (int ks = 0; ks < 8; ks++) {
            unsigned b0r, b1r;
            asm volatile("ldmatrix.sync.aligned.m8n8.x2.shared.b16 {%0,%1}, [%2];"
                : "=r"(b0r), "=r"(b1r) : "r"(lm + ks * 32));
            asm volatile(
                "mma.sync.aligned.m16n8k16.row.col.f32.f16.f16.f32 "
                "{%0,%1,%2,%3}, {%4,%5,%6,%7}, {%8,%9}, {%0,%1,%2,%3};"
                : "+f"(c0[0]), "+f"(c0[1]), "+f"(c0[2]), "+f"(c0[3])
                : "r"(Af[ks][0][0]), "r"(Af[ks][0][1]), "r"(Af[ks][0][2]), "r"(Af[ks][0][3]),
                  "r"(b0r), "r"(b1r));
            asm volatile(
                "mma.sync.aligned.m16n8k16.row.col.f32.f16.f16.f32 "
                "{%0,%1,%2,%3}, {%4,%5,%6,%7}, {%8,%9}, {%0,%1,%2,%3};"
                : "+f"(c1[0]), "+f"(c1[1]), "+f"(c1[2]), "+f"(c1[3])
                : "r"(Af[ks][1][0]), "r"(Af[ks][1][1]), "r"(Af[ks][1][2]), "r"(Af[ks][1][3]),
                  "r"(b0r), "r"(b1r));
        }

        float ii0 = fmaf(tanhap(c0[0]), 0.5f, 0.5f);
        float ii1 = fmaf(tanhap(c0[1]), 0.5f, 0.5f);
        float ff0 = fmaf(tanhap(c0[2]), 0.5f, 0.5f);
        float ff1 = fmaf(tanhap(c0[3]), 0.5f, 0.5f);
        float gg0 = tanhap(c1[0]);
        float gg1 = tanhap(c1[1]);
        float oo0 = fmaf(tanhap(c1[2]), 0.5f, 0.5f);
        float oo1 = fmaf(tanhap(c1[3]), 0.5f, 0.5f);

        cst0 = fmaf(ff0, cst0, ii0 * gg0);
        cst1 = fmaf(ff1, cst1, ii1 * gg1);
        h0v = oo0 * tanhap(cst0);
        h1v = oo1 * tanhap(cst1);

        __half hh0 = __float2half(h0v);
        __half hh1 = __float2half(h1v);
        hw[(2 * tg)     * HAS_ + hc] = hh0;
        hw[(2 * tg + 1) * HAS_ + hc] = hh1;

        g_y0h[((size_t)t * B_ + brow0) * (2 * H_) + dir * H_ + hc] = hh0;
        g_y0h[((size_t)t * B_ + brow1) * (2 * H_) + dir * H_ + hc] = hh1;

        if (s + 1 < T_ && tid < 32) {
            asm volatile("cp.async.wait_group 0;");
        }
        __syncthreads();
    }

    const int d = dir;
    hn[((size_t)d * B_ + brow0) * H_ + hc] = h0v;
    hn[((size_t)d * B_ + brow1) * H_ + hc] = h1v;
    cn[((size_t)d * B_ + brow0) * H_ + hc] = cst0;
    cn[((size_t)d * B_ + brow1) * H_ + hc] = cst1;
}

// ---------------- layer-1 scan with smem-staged gx ----------------
// gx[8,512] per step (16 KB, contiguous) staged via cp.async (2 per thread,
// coalesced), double-buffered; cell phase reads conflict-free LDS (stride 516).
// Replaces 8 scattered LDG/thread/step (32 L1tex wavefronts/warp).
__global__ __launch_bounds__(512) void lstm_scan_mma(
    const float* __restrict__ whhf, const float* __restrict__ whhb,
    float* __restrict__ y1, float* __restrict__ hn, float* __restrict__ cn)
{
    __shared__ __half hA[2 * 8 * HAS_];       // 4352 B
    __shared__ float  gsm[2 * 8 * GSP_];      // 33024 B

    const int tid  = threadIdx.x;
    const int lane = tid & 31;
    const int w    = tid >> 5;
    const int dir  = blockIdx.y;
    const int b0   = blockIdx.x * MB_;
    const int g4 = lane >> 2, tg = lane & 3;
    const float* __restrict__ whh = dir ? whhb : whhf;
    const float* __restrict__ gx  = g_gx[dir];

    unsigned Af[8][2][4];
    #pragma unroll
    for (int ks = 0; ks < 8; ks++)
        #pragma unroll
        for (int tl = 0; tl < 2; tl++) {
            const float* pA = whh + (size_t)((2 * tl)     * 128 + 8 * w + g4) * H_ + ks * 16 + tg * 2;
            const float* pB = whh + (size_t)((2 * tl + 1) * 128 + 8 * w + g4) * H_ + ks * 16 + tg * 2;
            float2 vA0 = *(const float2*)pA;
            float2 vB0 = *(const float2*)pB;
            float2 vA1 = *(const float2*)(pA + 8);
            float2 vB1 = *(const float2*)(pB + 8);
            __half2 h0 = __floats2half2_rn(vA0.x, vA0.y);
            __half2 h1 = __floats2half2_rn(vB0.x, vB0.y);
            __half2 h2 = __floats2half2_rn(vA1.x, vA1.y);
            __half2 h3 = __floats2half2_rn(vB1.x, vB1.y);
            Af[ks][tl][0] = *(unsigned*)&h0;
            Af[ks][tl][1] = *(unsigned*)&h1;
            Af[ks][tl][2] = *(unsigned*)&h2;
            Af[ks][tl][3] = *(unsigned*)&h3;
        }

    for (int p = tid; p < 2 * 8 * HAS_; p += 512) hA[p] = __float2half(0.f);

    const int hc    = 8 * w + g4;
    const int brow0 = b0 + 2 * tg;
    const int brow1 = brow0 + 1;
    float cst0 = 0.f, cst1 = 0.f;
    float h0 = 0.f, h1 = 0.f;

    const unsigned hA_base = (unsigned)__cvta_generic_to_shared(hA);
    const unsigned gS_base = (unsigned)__cvta_generic_to_shared(gsm);
    const unsigned lmB = hA_base + (((lane & 7) * HAS_) + (((lane >> 3) & 1) * 8)) * 2;
    const unsigned BUFB = 8 * HAS_ * 2;

    // gx staging map: thread -> (row = tid>>6, seg = tid&63), 32 B per thread
    const int grow = tid >> 6;
    const int gseg = tid & 63;

    auto stage_gx = [&](int t, int buf) {
        const float* src = gx + ((size_t)t * B_ + b0 + grow) * G_ + gseg * 8;
        unsigned dst = gS_base + (unsigned)((buf * 8 + grow) * GSP_ + gseg * 8) * 4;
        cp16(dst, src);
        cp16(dst + 16, src + 4);
        asm volatile("cp.async.commit_group;");
    };

    // preload step-0 gx into buf 0
    stage_gx(dir ? (T_ - 1) : 0, 0);
    asm volatile("cp.async.wait_group 0;");
    __syncthreads();

    for (int s = 0; s < T_; s++) {
        const int t = dir ? (T_ - 1 - s) : s;
        const int rb = s & 1;
        const unsigned lm = lmB + rb * BUFB;
        __half* hw = hA + (rb ^ 1) * 8 * HAS_;

        // kick next step's gx copy into the other buffer
        if (s + 1 < T_) {
            stage_gx(dir ? (T_ - 2 - s) : (s + 1), rb ^ 1);
        }

        float c0[4] = {0.f, 0.f, 0.f, 0.f};
        float c1[4] = {0.f, 0.f, 0.f, 0.f};

        #pragma unroll
        for (int ks = 0; ks < 8; ks++) {
            unsigned b0r, b1r;
            asm volatile("ldmatrix.sync.aligned.m8n8.x2.shared.b16 {%0,%1}, [%2];"
                : "=r"(b0r), "=r"(b1r) : "r"(lm + ks * 32));
            asm volatile(
                "mma.sync.aligned.m16n8k16.row.col.f32.f16.f16.f32 "
                "{%0,%1,%2,%3}, {%4,%5,%6,%7}, {%8,%9}, {%0,%1,%2,%3};"
                : "+f"(c0[0]), "+f"(c0[1]), "+f"(c0[2]), "+f"(c0[3])
                : "r"(Af[ks][0][0]), "r"(Af[ks][0][1]), "r"(Af[ks][0][2]), "r"(Af[ks][0][3]),
                  "r"(b0r), "r"(b1r));
            asm volatile(
                "mma.sync.aligned.m16n8k16.row.col.f32.f16.f16.f32 "
                "{%0,%1,%2,%3}, {%4,%5,%6,%7}, {%8,%9}, {%0,%1,%2,%3};"
                : "+f"(c1[0]), "+f"(c1[1]), "+f"(c1[2]), "+f"(c1[3])
                : "r"(Af[ks][1][0]), "r"(Af[ks][1][1]), "r"(Af[ks][1][2]), "r"(Af[ks][1][3]),
                  "r"(b0r), "r"(b1r));
        }

        // cell phase: gx from smem (conflict-free: GSP_=516)
        const float* gr = gsm + rb * 8 * GSP_;
        float xi0 = gr[(2 * tg)     * GSP_ + hc];
        float xi1 = gr[(2 * tg + 1) * GSP_ + hc];
        float xf0 = gr[(2 * tg)     * GSP_ + 128 + hc];
        float xf1 = gr[(2 * tg + 1) * GSP_ + 128 + hc];
        float xg0 = gr[(2 * tg)     * GSP_ + 256 + hc];
        float xg1 = gr[(2 * tg + 1) * GSP_ + 256 + hc];
        float xo0 = gr[(2 * tg)     * GSP_ + 384 + hc];
        float xo1 = gr[(2 * tg + 1) * GSP_ + 384 + hc];

        float ii0 = fmaf(tanhap(fmaf(c0[0], 0.5f, xi0)), 0.5f, 0.5f);
        float ii1 = fmaf(tanhap(fmaf(c0[1], 0.5f, xi1)), 0.5f, 0.5f);
        float ff0 = fmaf(tanhap(fmaf(c0[2], 0.5f, xf0)), 0.5f, 0.5f);
        float ff1 = fmaf(tanhap(fmaf(c0[3], 0.5f, xf1)), 0.5f, 0.5f);
        float gg0 = tanhap(c1[0] + xg0);
        float gg1 = tanhap(c1[1] + xg1);
        float oo0 = fmaf(tanhap(fmaf(c1[2], 0.5f, xo0)), 0.5f, 0.5f);
        float oo1 = fmaf(tanhap(fmaf(c1[3], 0.5f, xo1)), 0.5f, 0.5f);

        cst0 = fmaf(ff0, cst0, ii0 * gg0);
        cst1 = fmaf(ff1, cst1, ii1 * gg1);
        h0 = oo0 * tanhap(cst0);
        h1 = oo1 * tanhap(cst1);

        __half hh0 = __float2half(h0);
        __half hh1 = __float2half(h1);
        hw[(2 * tg)     * HAS_ + hc] = hh0;
        hw[(2 * tg + 1) * HAS_ + hc] = hh1;

        y1[((size_t)brow0 * T_ + t) * (2 * H_) + dir * H_ + hc] = h0;
        y1[((size_t)brow1 * T_ + t) * (2 * H_) + dir * H_ + hc] = h1;

        if (s + 1 < T_) {
            asm volatile("cp.async.wait_group 0;");
        }
        __syncthreads();
    }

    const int d = 2 + dir;   // layer 1
    hn[((size_t)d * B_ + brow0) * H_ + hc] = h0;
    hn[((size_t)d * B_ + brow1) * H_ + hc] = h1;
    cn[((size_t)d * B_ + brow0) * H_ + hc] = cst0;
    cn[((size_t)d * B_ + brow1) * H_ + hc] = cst1;
}

// ---------------- launch ----------------
extern "C" void kernel_launch(void* const* d_in, const int* in_sizes, int n_in,
                              void* d_out, int out_size) {
    const float* x     = (const float*)d_in[0];
    const float* wih0f = (const float*)d_in[1];
    const float* whh0f = (const float*)d_in[2];
    const float* b0f   = (const float*)d_in[3];
    const float* wih0b = (const float*)d_in[4];
    const float* whh0b = (const float*)d_in[5];
    const float* b0b   = (const float*)d_in[6];
    const float* wih1f = (const float*)d_in[7];
    const float* whh1f = (const float*)d_in[8];
    const float* b1f   = (const float*)d_in[9];
    const float* wih1b = (const float*)d_in[10];
    const float* whh1b = (const float*)d_in[11];
    const float* b1b   = (const float*)d_in[12];
    (void)in_sizes; (void)n_in; (void)out_size;

    float* out = (float*)d_out;
    float* y1 = out;
    float* hn = out + Y1SZ_;
    float* cn = hn + 4 * B_ * H_;

    // fp16 conversions
    conv_x_kernel<<<(BT_ * 32 + 255) / 256, 256>>>(x);
    conv_w1_kernel<<<(2 * G_ * 256 + 255) / 256, 256>>>(wih1f, wih1b);

    // layer 0: fused input-GEMM + scan (no gx materialization)
    lstm_scan_fused0<<<dim3(B_ / MB_, 2), 512>>>(wih0f, whh0f, b0f, wih0b, whh0b, b0b, hn, cn);

    // layer 1
    gemm_gx_kernel<<<dim3(8, BT_ / 128), 256>>>(b1f, b1b);
    lstm_scan_mma<<<dim3(B_ / MB_, 2), 512>>>(whh1f, whh1b, y1, hn, cn);
}

// round 11
// speedup vs baseline: 1.9959x; 1.0807x over previous
#include <cuda_runtime.h>
#include <cuda_fp16.h>
#include <cstdint>

#define B_  256
#define T_  512
#define I_  24
#define H_  128
#define G_  512           // 4*H
#define BT_ (B_*T_)       // 131072
#define MB_ 8             // batch rows per scan block
#define HAS_ 136          // hA row stride in halves (128 + 8 pad)
#define SAS_ 40           // GEMM smem row stride in halves (32 + 8 pad)
#define XS_  40           // x smem row stride in halves

static const size_t Y1SZ_ = (size_t)BT_ * 2 * H_;   // 33,554,432

// ---------------- scratch (no cudaMalloc allowed) ----------------
// gx layout: [t][bg(32)][j(512)][bp(8)] fp32 — scan reads are 256B-contiguous
// per warp (float2 over the bp pair), gemm writes are 32B-sector dense.
__device__ float  g_gx[2][(size_t)BT_ * G_];        // layer-1 gx
__device__ __half g_y0h[(size_t)BT_ * 2 * H_];      // 64 MB, rows r' = t*B + b
__device__ __half g_xh[(size_t)BT_ * 32];           // x padded 24->32, rows r' = t*B + b
__device__ __half g_w1h[2][G_ * 256];               // w_ih layer1, fp16

__device__ __forceinline__ float tanhap(float x) {
    float y; asm("tanh.approx.f32 %0, %1;" : "=f"(y) : "f"(x)); return y;
}
__device__ __forceinline__ void cp16(unsigned dst, const void* src) {
    asm volatile("cp.async.ca.shared.global [%0], [%1], 16;" :: "r"(dst), "l"(src));
}

// ---------------- conversion kernels ----------------
__global__ void conv_x_kernel(const float* __restrict__ x) {
    int idx = blockIdx.x * 256 + threadIdx.x;
    if (idx < BT_ * 32) {
        int r = idx >> 5, i = idx & 31;       // r' = t*256 + b
        int b = r & 255, t = r >> 8;
        g_xh[idx] = (i < I_) ? __float2half(x[((size_t)b * T_ + t) * I_ + i]) : __float2half(0.f);
    }
}

__global__ void conv_w1_kernel(const float* __restrict__ w1f, const float* __restrict__ w1b) {
    int idx = blockIdx.x * 256 + threadIdx.x;
    if (idx < 2 * G_ * 256) {
        int d = idx / (G_ * 256); int p = idx % (G_ * 256);
        const float* w = d ? w1b : w1f;
        g_w1h[d][p] = __float2half(w[p]);
    }
}

// ---------------- pipelined input GEMM (layer 1) ----------------
// Grid (8, BT/128): blockIdx.x = (dir<<2 | n-tile) fastest so A M-tiles are L2-hot.
__global__ __launch_bounds__(256) void gemm_gx_kernel(
    const float* __restrict__ biasf, const float* __restrict__ biasb)
{
    const int K = 256;
    __shared__ __half sA[2][128 * SAS_];
    __shared__ __half sW[2][128 * SAS_];

    const int dir = blockIdx.x >> 2;
    const __half* __restrict__ A = g_y0h;
    const __half* __restrict__ W = g_w1h[dir];
    const float* __restrict__ bias = dir ? biasb : biasf;
    float* __restrict__ gx = g_gx[dir];

    const int tid  = threadIdx.x;
    const int lane = tid & 31;
    const int warp = tid >> 5;
    const int warpM = warp & 3;
    const int warpN = warp >> 2;
    const int g4 = lane >> 2;
    const int tg = lane & 3;
    const int mblk = blockIdx.y * 128;
    const int nblk = (blockIdx.x & 3) * 128;
    const int nk = K >> 5;

    const unsigned sA_base = (unsigned)__cvta_generic_to_shared(sA);
    const unsigned sW_base = (unsigned)__cvta_generic_to_shared(sW);

    const int lrow = tid >> 2;
    const int lseg = tid & 3;

    auto load_stage = [&](int ks, int buf) {
        #pragma unroll
        for (int rr = 0; rr < 2; rr++) {
            int r = lrow + rr * 64;
            const __half* srcA = A + (size_t)(mblk + r) * K + ks * 32 + lseg * 8;
            const __half* srcW = W + (size_t)(nblk + r) * K + ks * 32 + lseg * 8;
            unsigned off = (unsigned)(buf * 128 * SAS_ + r * SAS_ + lseg * 8) * 2;
            cp16(sA_base + off, srcA);
            cp16(sW_base + off, srcW);
        }
        asm volatile("cp.async.commit_group;");
    };

    float acc[2][8][4];
    #pragma unroll
    for (int mf = 0; mf < 2; mf++)
        #pragma unroll
        for (int nf = 0; nf < 8; nf++)
            #pragma unroll
            for (int q = 0; q < 4; q++) acc[mf][nf][q] = 0.f;

    load_stage(0, 0);

    const unsigned lmA0 = sA_base + ((warpM * 32 + (lane & 15)) * SAS_ + (lane >> 4) * 8) * 2;
    const unsigned lmW0 = sW_base + ((warpN * 64 + (lane & 7)) * SAS_ + ((lane >> 3) & 1) * 8) * 2;

    for (int ks = 0; ks < nk; ks++) {
        const int buf = ks & 1;
        if (ks + 1 < nk) {
            load_stage(ks + 1, buf ^ 1);
            asm volatile("cp.async.wait_group 1;");
        } else {
            asm volatile("cp.async.wait_group 0;");
        }
        __syncthreads();

        const unsigned aBuf = lmA0 + buf * 128 * SAS_ * 2;
        const unsigned wBuf = lmW0 + buf * 128 * SAS_ * 2;

        #pragma unroll
        for (int kk = 0; kk < 2; kk++) {
            unsigned a[2][4];
            #pragma unroll
            for (int mf = 0; mf < 2; mf++) {
                asm volatile("ldmatrix.sync.aligned.m8n8.x4.shared.b16 {%0,%1,%2,%3}, [%4];"
                    : "=r"(a[mf][0]), "=r"(a[mf][1]), "=r"(a[mf][2]), "=r"(a[mf][3])
                    : "r"(aBuf + (mf * 16 * SAS_ + kk * 16) * 2));
            }
            #pragma unroll
            for (int nf = 0; nf < 8; nf++) {
                unsigned b0, b1;
                asm volatile("ldmatrix.sync.aligned.m8n8.x2.shared.b16 {%0,%1}, [%2];"
                    : "=r"(b0), "=r"(b1)
                    : "r"(wBuf + (nf * 8 * SAS_ + kk * 16) * 2));
                #pragma unroll
                for (int mf = 0; mf < 2; mf++) {
                    asm volatile(
                        "mma.sync.aligned.m16n8k16.row.col.f32.f16.f16.f32 "
                        "{%0,%1,%2,%3}, {%4,%5,%6,%7}, {%8,%9}, {%0,%1,%2,%3};"
                        : "+f"(acc[mf][nf][0]), "+f"(acc[mf][nf][1]),
                          "+f"(acc[mf][nf][2]), "+f"(acc[mf][nf][3])
                        : "r"(a[mf][0]), "r"(a[mf][1]), "r"(a[mf][2]), "r"(a[mf][3]),
                          "r"(b0), "r"(b1));
                }
            }
        }
        __syncthreads();
    }

    // epilogue -> gx[t][bg][j][bp]; lanes form 32B-sector-dense clusters
    const int t = mblk >> 8;
    const int bbase = mblk & 255;
    #pragma unroll
    for (int mf = 0; mf < 2; mf++) {
        int b1 = bbase + warpM * 32 + mf * 16 + g4;   // bp = g4
        int b2 = b1 + 8;
        #pragma unroll
        for (int nf = 0; nf < 8; nf++) {
            int n0 = nblk + warpN * 64 + nf * 8 + tg * 2;
            float sc = ((n0 >> 7) == 2) ? 1.f : 0.5f;
            float bv0 = bias[n0], bv1 = bias[n0 + 1];
            size_t o1 = (((size_t)t * 32 + (b1 >> 3)) * G_ + n0) * 8 + g4;
            gx[o1]     = sc * (acc[mf][nf][0] + bv0);
            gx[o1 + 8] = sc * (acc[mf][nf][1] + bv1);
            size_t o2 = (((size_t)t * 32 + (b2 >> 3)) * G_ + n0) * 8 + g4;
            gx[o2]     = sc * (acc[mf][nf][2] + bv0);
            gx[o2 + 8] = sc * (acc[mf][nf][3] + bv1);
        }
    }
}

// ---------------- layer-0 FUSED scan (ldsm.x4 merged; math identical) ----------------
__global__ __launch_bounds__(512) void lstm_scan_fused0(
    const float* __restrict__ wihf, const float* __restrict__ whhf, const float* __restrict__ bf_,
    const float* __restrict__ wihb, const float* __restrict__ whhb, const float* __restrict__ bb_,
    float* __restrict__ hn, float* __restrict__ cn)
{
    __shared__ __half hA[2 * 8 * HAS_];
    __shared__ __half xS[2 * 8 * XS_];

    const int tid  = threadIdx.x;
    const int lane = tid & 31;
    const int w    = tid >> 5;
    const int dir  = blockIdx.y;
    const int b0   = blockIdx.x * MB_;
    const int g4 = lane >> 2, tg = lane & 3;
    const float* __restrict__ whh  = dir ? whhb : whhf;
    const float* __restrict__ wih  = dir ? wihb : wihf;
    const float* __restrict__ bias = dir ? bb_ : bf_;

    unsigned Af[8][2][4];
    #pragma unroll
    for (int ks = 0; ks < 8; ks++)
        #pragma unroll
        for (int tl = 0; tl < 2; tl++) {
            const float* pA = whh + (size_t)((2 * tl)     * 128 + 8 * w + g4) * H_ + ks * 16 + tg * 2;
            const float* pB = whh + (size_t)((2 * tl + 1) * 128 + 8 * w + g4) * H_ + ks * 16 + tg * 2;
            float scA = (tl == 0) ? 0.5f : 1.0f;
            float scB = 0.5f;
            float2 vA0 = *(const float2*)pA;
            float2 vB0 = *(const float2*)pB;
            float2 vA1 = *(const float2*)(pA + 8);
            float2 vB1 = *(const float2*)(pB + 8);
            __half2 h0 = __floats2half2_rn(scA * vA0.x, scA * vA0.y);
            __half2 h1 = __floats2half2_rn(scB * vB0.x, scB * vB0.y);
            __half2 h2 = __floats2half2_rn(scA * vA1.x, scA * vA1.y);
            __half2 h3 = __floats2half2_rn(scB * vB1.x, scB * vB1.y);
            Af[ks][tl][0] = *(unsigned*)&h0;
            Af[ks][tl][1] = *(unsigned*)&h1;
            Af[ks][tl][2] = *(unsigned*)&h2;
            Af[ks][tl][3] = *(unsigned*)&h3;
        }

    unsigned Ax[2][2][4];
    #pragma unroll
    for (int ks = 0; ks < 2; ks++)
        #pragma unroll
        for (int tl = 0; tl < 2; tl++) {
            int rA = (2 * tl) * 128 + 8 * w + g4;
            int rB = (2 * tl + 1) * 128 + 8 * w + g4;
            float scA = (tl == 0) ? 0.5f : 1.0f;
            float scB = 0.5f;
            int k0 = ks * 16 + tg * 2;
            int k1 = k0 + 8;
            float2 vA0 = *(const float2*)(wih + (size_t)rA * I_ + k0);
            float2 vB0 = *(const float2*)(wih + (size_t)rB * I_ + k0);
            float2 vA1 = (k1 < I_) ? *(const float2*)(wih + (size_t)rA * I_ + k1) : make_float2(0.f, 0.f);
            float2 vB1 = (k1 < I_) ? *(const float2*)(wih + (size_t)rB * I_ + k1) : make_float2(0.f, 0.f);
            __half2 h0 = __floats2half2_rn(scA * vA0.x, scA * vA0.y);
            __half2 h1 = __floats2half2_rn(scB * vB0.x, scB * vB0.y);
            __half2 h2 = __floats2half2_rn(scA * vA1.x, scA * vA1.y);
            __half2 h3 = __floats2half2_rn(scB * vB1.x, scB * vB1.y);
            Ax[ks][tl][0] = *(unsigned*)&h0;
            Ax[ks][tl][1] = *(unsigned*)&h1;
            Ax[ks][tl][2] = *(unsigned*)&h2;
            Ax[ks][tl][3] = *(unsigned*)&h3;
        }

    const int hc = 8 * w + g4;
    const float bi = 0.5f * bias[hc];
    const float bfv = 0.5f * bias[128 + hc];
    const float bg  = bias[256 + hc];
    const float bo  = 0.5f * bias[384 + hc];

    for (int p = tid; p < 2 * 8 * HAS_; p += 512) hA[p] = __float2half(0.f);

    const int brow0 = b0 + 2 * tg;
    const int brow1 = brow0 + 1;
    float cst0 = 0.f, cst1 = 0.f;
    float h0v = 0.f, h1v = 0.f;

    const unsigned hA_base = (unsigned)__cvta_generic_to_shared(hA);
    const unsigned xS_base = (unsigned)__cvta_generic_to_shared(xS);
    // x4 B-ldsm: lanes 0-7/8-15/16-23/24-31 -> k offsets +0/+8/+16/+24
    const unsigned lmB4 = hA_base + (((lane & 7) * HAS_) + ((lane >> 3) & 3) * 8) * 2;
    const unsigned lmX4 = xS_base + (((lane & 7) * XS_)  + ((lane >> 3) & 3) * 8) * 2;
    const unsigned BUFB = 8 * HAS_ * 2;
    const unsigned XBUF = 8 * XS_ * 2;

    {
        int t0 = dir ? (T_ - 1) : 0;
        if (tid < 32) {
            int row = tid >> 2, seg = tid & 3;
            cp16(xS_base + (unsigned)(row * XS_ + seg * 8) * 2,
                 g_xh + ((size_t)t0 * B_ + b0 + row) * 32 + seg * 8);
            asm volatile("cp.async.commit_group;");
            asm volatile("cp.async.wait_group 0;");
        }
    }
    __syncthreads();

    for (int s = 0; s < T_; s++) {
        const int t = dir ? (T_ - 1 - s) : s;
        const int rb = s & 1;
        const unsigned lm = lmB4 + rb * BUFB;
        const unsigned lx = lmX4 + rb * XBUF;
        __half* hw = hA + (rb ^ 1) * 8 * HAS_;

        if (s + 1 < T_ && tid < 32) {
            int tn = dir ? (T_ - 2 - s) : (s + 1);
            int row = tid >> 2, seg = tid & 3;
            cp16(xS_base + (rb ^ 1) * XBUF + (unsigned)(row * XS_ + seg * 8) * 2,
                 g_xh + ((size_t)tn * B_ + b0 + row) * 32 + seg * 8);
            asm volatile("cp.async.commit_group;");
        }

        float c0[4] = {bi, bi, bfv, bfv};
        float c1[4] = {bg, bg, bo, bo};

        // x contribution: one x4 ldsm covers both k-steps (same order as before)
        {
            unsigned r0, r1, r2, r3;
            asm volatile("ldmatrix.sync.aligned.m8n8.x4.shared.b16 {%0,%1,%2,%3}, [%4];"
                : "=r"(r0), "=r"(r1), "=r"(r2), "=r"(r3) : "r"(lx));
            asm volatile("mma.sync.aligned.m16n8k16.row.col.f32.f16.f16.f32 "
                "{%0,%1,%2,%3}, {%4,%5,%6,%7}, {%8,%9}, {%0,%1,%2,%3};"
                : "+f"(c0[0]), "+f"(c0[1]), "+f"(c0[2]), "+f"(c0[3])
                : "r"(Ax[0][0][0]), "r"(Ax[0][0][1]), "r"(Ax[0][0][2]), "r"(Ax[0][0][3]),
                  "r"(r0), "r"(r1));
            asm volatile("mma.sync.aligned.m16n8k16.row.col.f32.f16.f16.f32 "
                "{%0,%1,%2,%3}, {%4,%5,%6,%7}, {%8,%9}, {%0,%1,%2,%3};"
                : "+f"(c1[0]), "+f"(c1[1]), "+f"(c1[2]), "+f"(c1[3])
                : "r"(Ax[0][1][0]), "r"(Ax[0][1][1]), "r"(Ax[0][1][2]), "r"(Ax[0][1][3]),
                  "r"(r0), "r"(r1));
            asm volatile("mma.sync.aligned.m16n8k16.row.col.f32.f16.f16.f32 "
                "{%0,%1,%2,%3}, {%4,%5,%6,%7}, {%8,%9}, {%0,%1,%2,%3};"
                : "+f"(c0[0]), "+f"(c0[1]), "+f"(c0[2]), "+f"(c0[3])
                : "r"(Ax[1][0][0]), "r"(Ax[1][0][1]), "r"(Ax[1][0][2]), "r"(Ax[1][0][3]),
                  "r"(r2), "r"(r3));
            asm volatile("mma.sync.aligned.m16n8k16.row.col.f32.f16.f16.f32 "
                "{%0,%1,%2,%3}, {%4,%5,%6,%7}, {%8,%9}, {%0,%1,%2,%3};"
                : "+f"(c1[0]), "+f"(c1[1]), "+f"(c1[2]), "+f"(c1[3])
                : "r"(Ax[1][1][0]), "r"(Ax[1][1][1]), "r"(Ax[1][1][2]), "r"(Ax[1][1][3]),
                  "r"(r2), "r"(r3));
        }

        // h contribution: 4 x4 ldsm, 16 MMA (same sequence as 8 x2 version)
        #pragma unroll
        for (int k2 = 0; k2 < 4; k2++) {
            unsigned r0, r1, r2, r3;
            asm volatile("ldmatrix.sync.aligned.m8n8.x4.shared.b16 {%0,%1,%2,%3}, [%4];"
                : "=r"(r0), "=r"(r1), "=r"(r2), "=r"(r3) : "r"(lm + k2 * 64));
            asm volatile("mma.sync.aligned.m16n8k16.row.col.f32.f16.f16.f32 "
                "{%0,%1,%2,%3}, {%4,%5,%6,%7}, {%8,%9}, {%0,%1,%2,%3};"
                : "+f"(c0[0]), "+f"(c0[1]), "+f"(c0[2]), "+f"(c0[3])
                : "r"(Af[2*k2][0][0]), "r"(Af[2*k2][0][1]), "r"(Af[2*k2][0][2]), "r"(Af[2*k2][0][3]),
                  "r"(r0), "r"(r1));
            asm volatile("mma.sync.aligned.m16n8k16.row.col.f32.f16.f16.f32 "
                "{%0,%1,%2,%3}, {%4,%5,%6,%7}, {%8,%9}, {%0,%1,%2,%3};"
                : "+f"(c1[0]), "+f"(c1[1]), "+f"(c1[2]), "+f"(c1[3])
                : "r"(Af[2*k2][1][0]), "r"(Af[2*k2][1][1]), "r"(Af[2*k2][1][2]), "r"(Af[2*k2][1][3]),
                  "r"(r0), "r"(r1));
            asm volatile("mma.sync.aligned.m16n8k16.row.col.f32.f16.f16.f32 "
                "{%0,%1,%2,%3}, {%4,%5,%6,%7}, {%8,%9}, {%0,%1,%2,%3};"
                : "+f"(c0[0]), "+f"(c0[1]), "+f"(c0[2]), "+f"(c0[3])
                : "r"(Af[2*k2+1][0][0]), "r"(Af[2*k2+1][0][1]), "r"(Af[2*k2+1][0][2]), "r"(Af[2*k2+1][0][3]),
                  "r"(r2), "r"(r3));
            asm volatile("mma.sync.aligned.m16n8k16.row.col.f32.f16.f16.f32 "
                "{%0,%1,%2,%3}, {%4,%5,%6,%7}, {%8,%9}, {%0,%1,%2,%3};"
                : "+f"(c1[0]), "+f"(c1[1]), "+f"(c1[2]), "+f"(c1[3])
                : "r"(Af[2*k2+1][1][0]), "r"(Af[2*k2+1][1][1]), "r"(Af[2*k2+1][1][2]), "r"(Af[2*k2+1][1][3]),
                  "r"(r2), "r"(r3));
        }

        float ii0 = fmaf(tanhap(c0[0]), 0.5f, 0.5f);
        float ii1 = fmaf(tanhap(c0[1]), 0.5f, 0.5f);
        float ff0 = fmaf(tanhap(c0[2]), 0.5f, 0.5f);
        float ff1 = fmaf(tanhap(c0[3]), 0.5f, 0.5f);
        float gg0 = tanhap(c1[0]);
        float gg1 = tanhap(c1[1]);
        float oo0 = fmaf(tanhap(c1[2]), 0.5f, 0.5f);
        float oo1 = fmaf(tanhap(c1[3]), 0.5f, 0.5f);

        cst0 = fmaf(ff0, cst0, ii0 * gg0);
        cst1 = fmaf(ff1, cst1, ii1 * gg1);
        h0v = oo0 * tanhap(cst0);
        h1v = oo1 * tanhap(cst1);

        __half hh0 = __float2half(h0v);
        __half hh1 = __float2half(h1v);
        hw[(2 * tg)     * HAS_ + hc] = hh0;
        hw[(2 * tg + 1) * HAS_ + hc] = hh1;

        g_y0h[((size_t)t * B_ + brow0) * (2 * H_) + dir * H_ + hc] = hh0;
        g_y0h[((size_t)t * B_ + brow1) * (2 * H_) + dir * H_ + hc] = hh1;

        if (s + 1 < T_ && tid < 32) {
            asm volatile("cp.async.wait_group 0;");
        }
        __syncthreads();
    }

    const int d = dir;
    hn[((size_t)d * B_ + brow0) * H_ + hc] = h0v;
    hn[((size_t)d * B_ + brow1) * H_ + hc] = h1v;
    cn[((size_t)d * B_ + brow0) * H_ + hc] = cst0;
    cn[((size_t)d * B_ + brow1) * H_ + hc] = cst1;
}

// ---------------- layer-1 scan: direct coalesced gx loads (no smem staging) ----
// gx[t][bg][j][bp]: per warp each gate load spans 256 B contiguous -> LDG.64,
// register double-buffered. smem = hA only.
__global__ __launch_bounds__(512) void lstm_scan_mma(
    const float* __restrict__ whhf, const float* __restrict__ whhb,
    float* __restrict__ y1, float* __restrict__ hn, float* __restrict__ cn)
{
    __shared__ __half hA[2 * 8 * HAS_];

    const int tid  = threadIdx.x;
    const int lane = tid & 31;
    const int w    = tid >> 5;
    const int dir  = blockIdx.y;
    const int b0   = blockIdx.x * MB_;
    const int g4 = lane >> 2, tg = lane & 3;
    const float* __restrict__ whh = dir ? whhb : whhf;
    const float* __restrict__ gx  = g_gx[dir];

    unsigned Af[8][2][4];
    #pragma unroll
    for (int ks = 0; ks < 8; ks++)
        #pragma unroll
        for (int tl = 0; tl < 2; tl++) {
            const float* pA = whh + (size_t)((2 * tl)     * 128 + 8 * w + g4) * H_ + ks * 16 + tg * 2;
            const float* pB = whh + (size_t)((2 * tl + 1) * 128 + 8 * w + g4) * H_ + ks * 16 + tg * 2;
            float2 vA0 = *(const float2*)pA;
            float2 vB0 = *(const float2*)pB;
            float2 vA1 = *(const float2*)(pA + 8);
            float2 vB1 = *(const float2*)(pB + 8);
            __half2 h0 = __floats2half2_rn(vA0.x, vA0.y);
            __half2 h1 = __floats2half2_rn(vB0.x, vB0.y);
            __half2 h2 = __floats2half2_rn(vA1.x, vA1.y);
            __half2 h3 = __floats2half2_rn(vB1.x, vB1.y);
            Af[ks][tl][0] = *(unsigned*)&h0;
            Af[ks][tl][1] = *(unsigned*)&h1;
            Af[ks][tl][2] = *(unsigned*)&h2;
            Af[ks][tl][3] = *(unsigned*)&h3;
        }

    for (int p = tid; p < 2 * 8 * HAS_; p += 512) hA[p] = __float2half(0.f);

    const int hc    = 8 * w + g4;
    const int brow0 = b0 + 2 * tg;
    const int brow1 = brow0 + 1;
    float cst0 = 0.f, cst1 = 0.f;
    float h0 = 0.f, h1 = 0.f;

    const unsigned hA_base = (unsigned)__cvta_generic_to_shared(hA);
    const unsigned lmB4 = hA_base + (((lane & 7) * HAS_) + ((lane >> 3) & 3) * 8) * 2;
    const unsigned BUFB = 8 * HAS_ * 2;

    // per-thread gx base for this batch group: + j*8 per gate/col, + 2tg for bp pair
    const int bg0 = b0 >> 3;
    const float* gxb = gx + 2 * tg;

    __syncthreads();

    float2 xi, xf, xg, xo;
    {
        int t0 = dir ? (T_ - 1) : 0;
        const float* p = gxb + ((size_t)t0 * 32 + bg0) * G_ * 8;
        xi = *(const float2*)(p + (0 * 128 + hc) * 8);
        xf = *(const float2*)(p + (1 * 128 + hc) * 8);
        xg = *(const float2*)(p + (2 * 128 + hc) * 8);
        xo = *(const float2*)(p + (3 * 128 + hc) * 8);
    }

    for (int s = 0; s < T_; s++) {
        const int t = dir ? (T_ - 1 - s) : s;
        const int rb = s & 1;
        const unsigned lm = lmB4 + rb * BUFB;
        __half* hw = hA + (rb ^ 1) * 8 * HAS_;

        float2 ni, nf2, ng, no;
        if (s + 1 < T_) {
            int tn = dir ? (T_ - 2 - s) : (s + 1);
            const float* p = gxb + ((size_t)tn * 32 + bg0) * G_ * 8;
            ni  = *(const float2*)(p + (0 * 128 + hc) * 8);
            nf2 = *(const float2*)(p + (1 * 128 + hc) * 8);
            ng  = *(const float2*)(p + (2 * 128 + hc) * 8);
            no  = *(const float2*)(p + (3 * 128 + hc) * 8);
        } else {
            ni = nf2 = ng = no = make_float2(0.f, 0.f);
        }

        float c0[4] = {0.f, 0.f, 0.f, 0.f};
        float c1[4] = {0.f, 0.f, 0.f, 0.f};

        #pragma unroll
        for (int k2 = 0; k2 < 4; k2++) {
            unsigned r0, r1, r2, r3;
            asm volatile("ldmatrix.sync.aligned.m8n8.x4.shared.b16 {%0,%1,%2,%3}, [%4];"
                : "=r"(r0), "=r"(r1), "=r"(r2), "=r"(r3) : "r"(lm + k2 * 64));
            asm volatile("mma.sync.aligned.m16n8k16.row.col.f32.f16.f16.f32 "
                "{%0,%1,%2,%3}, {%4,%5,%6,%7}, {%8,%9}, {%0,%1,%2,%3};"
                : "+f"(c0[0]), "+f"(c0[1]), "+f"(c0[2]), "+f"(c0[3])
                : "r"(Af[2*k2][0][0]), "r"(Af[2*k2][0][1]), "r"(Af[2*k2][0][2]), "r"(Af[2*k2][0][3]),
                  "r"(r0), "r"(r1));
            asm volatile("mma.sync.aligned.m16n8k16.row.col.f32.f16.f16.f32 "
                "{%0,%1,%2,%3}, {%4,%5,%6,%7}, {%8,%9}, {%0,%1,%2,%3};"
                : "+f"(c1[0]), "+f"(c1[1]), "+f"(c1[2]), "+f"(c1[3])
                : "r"(Af[2*k2][1][0]), "r"(Af[2*k2][1][1]), "r"(Af[2*k2][1][2]), "r"(Af[2*k2][1][3]),
                  "r"(r0), "r"(r1));
            asm volatile("mma.sync.aligned.m16n8k16.row.col.f32.f16.f16.f32 "
                "{%0,%1,%2,%3}, {%4,%5,%6,%7}, {%8,%9}, {%0,%1,%2,%3};"
                : "+f"(c0[0]), "+f"(c0[1]), "+f"(c0[2]), "+f"(c0[3])
                : "r"(Af[2*k2+1][0][0]), "r"(Af[2*k2+1][0][1]), "r"(Af[2*k2+1][0][2]), "r"(Af[2*k2+1][0][3]),
                  "r"(r2), "r"(r3));
            asm volatile("mma.sync.aligned.m16n8k16.row.col.f32.f16.f16.f32 "
                "{%0,%1,%2,%3}, {%4,%5,%6,%7}, {%8,%9}, {%0,%1,%2,%3};"
                : "+f"(c1[0]), "+f"(c1[1]), "+f"(c1[2]), "+f"(c1[3])
                : "r"(Af[2*k2+1][1][0]), "r"(Af[2*k2+1][1][1]), "r"(Af[2*k2+1][1][2]), "r"(Af[2*k2+1][1][3]),
                  "r"(r2), "r"(r3));
        }

        float ii0 = fmaf(tanhap(fmaf(c0[0], 0.5f, xi.x)), 0.5f, 0.5f);
        float ii1 = fmaf(tanhap(fmaf(c0[1], 0.5f, xi.y)), 0.5f, 0.5f);
        float ff0 = fmaf(tanhap(fmaf(c0[2], 0.5f, xf.x)), 0.5f, 0.5f);
        float ff1 = fmaf(tanhap(fmaf(c0[3], 0.5f, xf.y)), 0.5f, 0.5f);
        float gg0 = tanhap(c1[0] + xg.x);
        float gg1 = tanhap(c1[1] + xg.y);
        float oo0 = fmaf(tanhap(fmaf(c1[2], 0.5f, xo.x)), 0.5f, 0.5f);
        float oo1 = fmaf(tanhap(fmaf(c1[3], 0.5f, xo.y)), 0.5f, 0.5f);

        cst0 = fmaf(ff0, cst0, ii0 * gg0);
        cst1 = fmaf(ff1, cst1, ii1 * gg1);
        h0 = oo0 * tanhap(cst0);
        h1 = oo1 * tanhap(cst1);

        __half hh0 = __float2half(h0);
        __half hh1 = __float2half(h1);
        hw[(2 * tg)     * HAS_ + hc] = hh0;
        hw[(2 * tg + 1) * HAS_ + hc] = hh1;

        y1[((size_t)brow0 * T_ + t) * (2 * H_) + dir * H_ + hc] = h0;
        y1[((size_t)brow1 * T_ + t) * (2 * H_) + dir * H_ + hc] = h1;

        xi = ni; xf = nf2; xg = ng; xo = no;
        __syncthreads();
    }

    const int d = 2 + dir;   // layer 1
    hn[((size_t)d * B_ + brow0) * H_ + hc] = h0;
    hn[((size_t)d * B_ + brow1) * H_ + hc] = h1;
    cn[((size_t)d * B_ + brow0) * H_ + hc] = cst0;
    cn[((size_t)d * B_ + brow1) * H_ + hc] = cst1;
}

// ---------------- launch ----------------
extern "C" void kernel_launch(void* const* d_in, const int* in_sizes, int n_in,
                              void* d_out, int out_size) {
    const float* x     = (const float*)d_in[0];
    const float* wih0f = (const float*)d_in[1];
    const float* whh0f = (const float*)d_in[2];
    const float* b0f   = (const float*)d_in[3];
    const float* wih0b = (const float*)d_in[4];
    const float* whh0b = (const float*)d_in[5];
    const float* b0b   = (const float*)d_in[6];
    const float* wih1f = (const float*)d_in[7];
    const float* whh1f = (const float*)d_in[8];
    const float* b1f   = (const float*)d_in[9];
    const float* wih1b = (const float*)d_in[10];
    const float* whh1b = (const float*)d_in[11];
    const float* b1b   = (const float*)d_in[12];
    (void)in_sizes; (void)n_in; (void)out_size;

    float* out = (float*)d_out;
    float* y1 = out;
    float* hn = out + Y1SZ_;
    float* cn = hn + 4 * B_ * H_;

    // fp16 conversions
    conv_x_kernel<<<(BT_ * 32 + 255) / 256, 256>>>(x);
    conv_w1_kernel<<<(2 * G_ * 256 + 255) / 256, 256>>>(wih1f, wih1b);

    // layer 0: fused input-GEMM + scan (no gx materialization)
    lstm_scan_fused0<<<dim3(B_ / MB_, 2), 512>>>(wih0f, whh0f, b0f, wih0b, whh0b, b0b, hn, cn);

    // layer 1
    gemm_gx_kernel<<<dim3(8, BT_ / 128), 256>>>(b1f, b1b);
    lstm_scan_mma<<<dim3(B_ / MB_, 2), 512>>>(whh1f, whh1b, y1, hn, cn);
}

// round 12
// speedup vs baseline: 2.0421x; 1.0231x over previous
#include <cuda_runtime.h>
#include <cuda_fp16.h>
#include <cstdint>

#define B_  256
#define T_  512
#define I_  24
#define H_  128
#define G_  512           // 4*H
#define BT_ (B_*T_)       // 131072
#define MB_ 8             // batch rows per scan block
#define HAS_ 136          // hA row stride in halves (128 + 8 pad)
#define SAS_ 40           // GEMM smem row stride in halves (32 + 8 pad)
#define XS_  40           // x smem row stride in halves
#define YBS_ 132          // ybuf row stride in floats (128 + 4 pad)

static const size_t Y1SZ_ = (size_t)BT_ * 2 * H_;   // 33,554,432

// ---------------- scratch (no cudaMalloc allowed) ----------------
// gx layout: [t][bg(32)][j(512)][bp(8)] fp32.
__device__ float  g_gx[2][(size_t)BT_ * G_];        // layer-1 gx
__device__ __half g_y0h[(size_t)BT_ * 2 * H_];      // 64 MB, rows r' = t*B + b
__device__ __half g_xh[(size_t)BT_ * 32];           // x padded 24->32, rows r' = t*B + b
__device__ __half g_w1h[2][G_ * 256];               // w_ih layer1, fp16

__device__ __forceinline__ float tanhap(float x) {
    float y; asm("tanh.approx.f32 %0, %1;" : "=f"(y) : "f"(x)); return y;
}
__device__ __forceinline__ void cp16(unsigned dst, const void* src) {
    asm volatile("cp.async.ca.shared.global [%0], [%1], 16;" :: "r"(dst), "l"(src));
}

// ---------------- conversion kernels ----------------
__global__ void conv_x_kernel(const float* __restrict__ x) {
    int idx = blockIdx.x * 256 + threadIdx.x;
    if (idx < BT_ * 32) {
        int r = idx >> 5, i = idx & 31;       // r' = t*256 + b
        int b = r & 255, t = r >> 8;
        g_xh[idx] = (i < I_) ? __float2half(x[((size_t)b * T_ + t) * I_ + i]) : __float2half(0.f);
    }
}

__global__ void conv_w1_kernel(const float* __restrict__ w1f, const float* __restrict__ w1b) {
    int idx = blockIdx.x * 256 + threadIdx.x;
    if (idx < 2 * G_ * 256) {
        int d = idx / (G_ * 256); int p = idx % (G_ * 256);
        const float* w = d ? w1b : w1f;
        g_w1h[d][p] = __float2half(w[p]);
    }
}

// ---------------- pipelined input GEMM (layer 1) ----------------
__global__ __launch_bounds__(256) void gemm_gx_kernel(
    const float* __restrict__ biasf, const float* __restrict__ biasb)
{
    const int K = 256;
    __shared__ __half sA[2][128 * SAS_];
    __shared__ __half sW[2][128 * SAS_];

    const int dir = blockIdx.x >> 2;
    const __half* __restrict__ A = g_y0h;
    const __half* __restrict__ W = g_w1h[dir];
    const float* __restrict__ bias = dir ? biasb : biasf;
    float* __restrict__ gx = g_gx[dir];

    const int tid  = threadIdx.x;
    const int lane = tid & 31;
    const int warp = tid >> 5;
    const int warpM = warp & 3;
    const int warpN = warp >> 2;
    const int g4 = lane >> 2;
    const int tg = lane & 3;
    const int mblk = blockIdx.y * 128;
    const int nblk = (blockIdx.x & 3) * 128;
    const int nk = K >> 5;

    const unsigned sA_base = (unsigned)__cvta_generic_to_shared(sA);
    const unsigned sW_base = (unsigned)__cvta_generic_to_shared(sW);

    const int lrow = tid >> 2;
    const int lseg = tid & 3;

    auto load_stage = [&](int ks, int buf) {
        #pragma unroll
        for (int rr = 0; rr < 2; rr++) {
            int r = lrow + rr * 64;
            const __half* srcA = A + (size_t)(mblk + r) * K + ks * 32 + lseg * 8;
            const __half* srcW = W + (size_t)(nblk + r) * K + ks * 32 + lseg * 8;
            unsigned off = (unsigned)(buf * 128 * SAS_ + r * SAS_ + lseg * 8) * 2;
            cp16(sA_base + off, srcA);
            cp16(sW_base + off, srcW);
        }
        asm volatile("cp.async.commit_group;");
    };

    float acc[2][8][4];
    #pragma unroll
    for (int mf = 0; mf < 2; mf++)
        #pragma unroll
        for (int nf = 0; nf < 8; nf++)
            #pragma unroll
            for (int q = 0; q < 4; q++) acc[mf][nf][q] = 0.f;

    load_stage(0, 0);

    const unsigned lmA0 = sA_base + ((warpM * 32 + (lane & 15)) * SAS_ + (lane >> 4) * 8) * 2;
    // W x4: lanes 0-7 row+0/col0, 8-15 row+0/col8, 16-23 row+8/col0, 24-31 row+8/col8
    const unsigned lmW0 = sW_base + ((warpN * 64 + ((lane >> 4) & 1) * 8 + (lane & 7)) * SAS_
                                     + ((lane >> 3) & 1) * 8) * 2;

    for (int ks = 0; ks < nk; ks++) {
        const int buf = ks & 1;
        if (ks + 1 < nk) {
            load_stage(ks + 1, buf ^ 1);
            asm volatile("cp.async.wait_group 1;");
        } else {
            asm volatile("cp.async.wait_group 0;");
        }
        __syncthreads();

        const unsigned aBuf = lmA0 + buf * 128 * SAS_ * 2;
        const unsigned wBuf = lmW0 + buf * 128 * SAS_ * 2;

        #pragma unroll
        for (int kk = 0; kk < 2; kk++) {
            unsigned a[2][4];
            #pragma unroll
            for (int mf = 0; mf < 2; mf++) {
                asm volatile("ldmatrix.sync.aligned.m8n8.x4.shared.b16 {%0,%1,%2,%3}, [%4];"
                    : "=r"(a[mf][0]), "=r"(a[mf][1]), "=r"(a[mf][2]), "=r"(a[mf][3])
                    : "r"(aBuf + (mf * 16 * SAS_ + kk * 16) * 2));
            }
            #pragma unroll
            for (int nf2 = 0; nf2 < 4; nf2++) {
                unsigned b0, b1, b2, b3;   // (b0,b1) = frag nf=2*nf2, (b2,b3) = nf+1
                asm volatile("ldmatrix.sync.aligned.m8n8.x4.shared.b16 {%0,%1,%2,%3}, [%4];"
                    : "=r"(b0), "=r"(b1), "=r"(b2), "=r"(b3)
                    : "r"(wBuf + (nf2 * 16 * SAS_ + kk * 16) * 2));
                #pragma unroll
                for (int mf = 0; mf < 2; mf++) {
                    asm volatile(
                        "mma.sync.aligned.m16n8k16.row.col.f32.f16.f16.f32 "
                        "{%0,%1,%2,%3}, {%4,%5,%6,%7}, {%8,%9}, {%0,%1,%2,%3};"
                        : "+f"(acc[mf][2*nf2][0]), "+f"(acc[mf][2*nf2][1]),
                          "+f"(acc[mf][2*nf2][2]), "+f"(acc[mf][2*nf2][3])
                        : "r"(a[mf][0]), "r"(a[mf][1]), "r"(a[mf][2]), "r"(a[mf][3]),
                          "r"(b0), "r"(b1));
                    asm volatile(
                        "mma.sync.aligned.m16n8k16.row.col.f32.f16.f16.f32 "
                        "{%0,%1,%2,%3}, {%4,%5,%6,%7}, {%8,%9}, {%0,%1,%2,%3};"
                        : "+f"(acc[mf][2*nf2+1][0]), "+f"(acc[mf][2*nf2+1][1]),
                          "+f"(acc[mf][2*nf2+1][2]), "+f"(acc[mf][2*nf2+1][3])
                        : "r"(a[mf][0]), "r"(a[mf][1]), "r"(a[mf][2]), "r"(a[mf][3]),
                          "r"(b2), "r"(b3));
                }
            }
        }
        __syncthreads();
    }

    // epilogue -> gx[t][bg][j][bp]
    const int t = mblk >> 8;
    const int bbase = mblk & 255;
    #pragma unroll
    for (int mf = 0; mf < 2; mf++) {
        int b1 = bbase + warpM * 32 + mf * 16 + g4;
        int b2 = b1 + 8;
        #pragma unroll
        for (int nf = 0; nf < 8; nf++) {
            int n0 = nblk + warpN * 64 + nf * 8 + tg * 2;
            float sc = ((n0 >> 7) == 2) ? 1.f : 0.5f;
            float bv0 = bias[n0], bv1 = bias[n0 + 1];
            size_t o1 = (((size_t)t * 32 + (b1 >> 3)) * G_ + n0) * 8 + g4;
            gx[o1]     = sc * (acc[mf][nf][0] + bv0);
            gx[o1 + 8] = sc * (acc[mf][nf][1] + bv1);
            size_t o2 = (((size_t)t * 32 + (b2 >> 3)) * G_ + n0) * 8 + g4;
            gx[o2]     = sc * (acc[mf][nf][2] + bv0);
            gx[o2 + 8] = sc * (acc[mf][nf][3] + bv1);
        }
    }
}

// ---------------- layer-0 FUSED scan; deferred cooperative y0 write ----------------
__global__ __launch_bounds__(512) void lstm_scan_fused0(
    const float* __restrict__ wihf, const float* __restrict__ whhf, const float* __restrict__ bf_,
    const float* __restrict__ wihb, const float* __restrict__ whhb, const float* __restrict__ bb_,
    float* __restrict__ hn, float* __restrict__ cn)
{
    __shared__ __half hA[2 * 8 * HAS_];
    __shared__ __half xS[2 * 8 * XS_];

    const int tid  = threadIdx.x;
    const int lane = tid & 31;
    const int w    = tid >> 5;
    const int dir  = blockIdx.y;
    const int b0   = blockIdx.x * MB_;
    const int g4 = lane >> 2, tg = lane & 3;
    const float* __restrict__ whh  = dir ? whhb : whhf;
    const float* __restrict__ wih  = dir ? wihb : wihf;
    const float* __restrict__ bias = dir ? bb_ : bf_;

    unsigned Af[8][2][4];
    #pragma unroll
    for (int ks = 0; ks < 8; ks++)
        #pragma unroll
        for (int tl = 0; tl < 2; tl++) {
            const float* pA = whh + (size_t)((2 * tl)     * 128 + 8 * w + g4) * H_ + ks * 16 + tg * 2;
            const float* pB = whh + (size_t)((2 * tl + 1) * 128 + 8 * w + g4) * H_ + ks * 16 + tg * 2;
            float scA = (tl == 0) ? 0.5f : 1.0f;
            float scB = 0.5f;
            float2 vA0 = *(const float2*)pA;
            float2 vB0 = *(const float2*)pB;
            float2 vA1 = *(const float2*)(pA + 8);
            float2 vB1 = *(const float2*)(pB + 8);
            __half2 h0 = __floats2half2_rn(scA * vA0.x, scA * vA0.y);
            __half2 h1 = __floats2half2_rn(scB * vB0.x, scB * vB0.y);
            __half2 h2 = __floats2half2_rn(scA * vA1.x, scA * vA1.y);
            __half2 h3 = __floats2half2_rn(scB * vB1.x, scB * vB1.y);
            Af[ks][tl][0] = *(unsigned*)&h0;
            Af[ks][tl][1] = *(unsigned*)&h1;
            Af[ks][tl][2] = *(unsigned*)&h2;
            Af[ks][tl][3] = *(unsigned*)&h3;
        }

    unsigned Ax[2][2][4];
    #pragma unroll
    for (int ks = 0; ks < 2; ks++)
        #pragma unroll
        for (int tl = 0; tl < 2; tl++) {
            int rA = (2 * tl) * 128 + 8 * w + g4;
            int rB = (2 * tl + 1) * 128 + 8 * w + g4;
            float scA = (tl == 0) ? 0.5f : 1.0f;
            float scB = 0.5f;
            int k0 = ks * 16 + tg * 2;
            int k1 = k0 + 8;
            float2 vA0 = *(const float2*)(wih + (size_t)rA * I_ + k0);
            float2 vB0 = *(const float2*)(wih + (size_t)rB * I_ + k0);
            float2 vA1 = (k1 < I_) ? *(const float2*)(wih + (size_t)rA * I_ + k1) : make_float2(0.f, 0.f);
            float2 vB1 = (k1 < I_) ? *(const float2*)(wih + (size_t)rB * I_ + k1) : make_float2(0.f, 0.f);
            __half2 h0 = __floats2half2_rn(scA * vA0.x, scA * vA0.y);
            __half2 h1 = __floats2half2_rn(scB * vB0.x, scB * vB0.y);
            __half2 h2 = __floats2half2_rn(scA * vA1.x, scA * vA1.y);
            __half2 h3 = __floats2half2_rn(scB * vB1.x, scB * vB1.y);
            Ax[ks][tl][0] = *(unsigned*)&h0;
            Ax[ks][tl][1] = *(unsigned*)&h1;
            Ax[ks][tl][2] = *(unsigned*)&h2;
            Ax[ks][tl][3] = *(unsigned*)&h3;
        }

    const int hc = 8 * w + g4;
    const float bi = 0.5f * bias[hc];
    const float bfv = 0.5f * bias[128 + hc];
    const float bg  = bias[256 + hc];
    const float bo  = 0.5f * bias[384 + hc];

    for (int p = tid; p < 2 * 8 * HAS_; p += 512) hA[p] = __float2half(0.f);

    const int brow0 = b0 + 2 * tg;
    const int brow1 = brow0 + 1;
    float cst0 = 0.f, cst1 = 0.f;
    float h0v = 0.f, h1v = 0.f;

    const unsigned hA_base = (unsigned)__cvta_generic_to_shared(hA);
    const unsigned xS_base = (unsigned)__cvta_generic_to_shared(xS);
    const unsigned lmB4 = hA_base + (((lane & 7) * HAS_) + ((lane >> 3) & 3) * 8) * 2;
    const unsigned lmX4 = xS_base + (((lane & 7) * XS_)  + ((lane >> 3) & 3) * 8) * 2;
    const unsigned BUFB = 8 * HAS_ * 2;
    const unsigned XBUF = 8 * XS_ * 2;

    // deferred-write mapping: row = tid>>6, 2 half cols per thread
    const int yr = tid >> 6;
    const int yc = (tid & 63) * 2;

    {
        int t0 = dir ? (T_ - 1) : 0;
        if (tid < 32) {
            int row = tid >> 2, seg = tid & 3;
            cp16(xS_base + (unsigned)(row * XS_ + seg * 8) * 2,
                 g_xh + ((size_t)t0 * B_ + b0 + row) * 32 + seg * 8);
            asm volatile("cp.async.commit_group;");
            asm volatile("cp.async.wait_group 0;");
        }
    }
    __syncthreads();

    for (int s = 0; s < T_; s++) {
        const int t = dir ? (T_ - 1 - s) : s;
        const int rb = s & 1;
        const unsigned lm = lmB4 + rb * BUFB;
        const unsigned lx = lmX4 + rb * XBUF;
        __half* hw = hA + (rb ^ 1) * 8 * HAS_;

        if (s + 1 < T_ && tid < 32) {
            int tn = dir ? (T_ - 2 - s) : (s + 1);
            int row = tid >> 2, seg = tid & 3;
            cp16(xS_base + (rb ^ 1) * XBUF + (unsigned)(row * XS_ + seg * 8) * 2,
                 g_xh + ((size_t)tn * B_ + b0 + row) * 32 + seg * 8);
            asm volatile("cp.async.commit_group;");
        }

        // deferred y0 write: h(s-1) lives in hA buf rb (the MMA read buffer)
        if (s > 0) {
            int tp = dir ? (T_ - s) : (s - 1);
            __half2 hv = *(__half2*)&hA[rb * 8 * HAS_ + yr * HAS_ + yc];
            *(__half2*)&g_y0h[((size_t)tp * B_ + b0 + yr) * (2 * H_) + dir * H_ + yc] = hv;
        }

        float c0[4] = {bi, bi, bfv, bfv};
        float c1[4] = {bg, bg, bo, bo};

        {
            unsigned r0, r1, r2, r3;
            asm volatile("ldmatrix.sync.aligned.m8n8.x4.shared.b16 {%0,%1,%2,%3}, [%4];"
                : "=r"(r0), "=r"(r1), "=r"(r2), "=r"(r3) : "r"(lx));
            asm volatile("mma.sync.aligned.m16n8k16.row.col.f32.f16.f16.f32 "
                "{%0,%1,%2,%3}, {%4,%5,%6,%7}, {%8,%9}, {%0,%1,%2,%3};"
                : "+f"(c0[0]), "+f"(c0[1]), "+f"(c0[2]), "+f"(c0[3])
                : "r"(Ax[0][0][0]), "r"(Ax[0][0][1]), "r"(Ax[0][0][2]), "r"(Ax[0][0][3]),
                  "r"(r0), "r"(r1));
            asm volatile("mma.sync.aligned.m16n8k16.row.col.f32.f16.f16.f32 "
                "{%0,%1,%2,%3}, {%4,%5,%6,%7}, {%8,%9}, {%0,%1,%2,%3};"
                : "+f"(c1[0]), "+f"(c1[1]), "+f"(c1[2]), "+f"(c1[3])
                : "r"(Ax[0][1][0]), "r"(Ax[0][1][1]), "r"(Ax[0][1][2]), "r"(Ax[0][1][3]),
                  "r"(r0), "r"(r1));
            asm volatile("mma.sync.aligned.m16n8k16.row.col.f32.f16.f16.f32 "
                "{%0,%1,%2,%3}, {%4,%5,%6,%7}, {%8,%9}, {%0,%1,%2,%3};"
                : "+f"(c0[0]), "+f"(c0[1]), "+f"(c0[2]), "+f"(c0[3])
                : "r"(Ax[1][0][0]), "r"(Ax[1][0][1]), "r"(Ax[1][0][2]), "r"(Ax[1][0][3]),
                  "r"(r2), "r"(r3));
            asm volatile("mma.sync.aligned.m16n8k16.row.col.f32.f16.f16.f32 "
                "{%0,%1,%2,%3}, {%4,%5,%6,%7}, {%8,%9}, {%0,%1,%2,%3};"
                : "+f"(c1[0]), "+f"(c1[1]), "+f"(c1[2]), "+f"(c1[3])
                : "r"(Ax[1][1][0]), "r"(Ax[1][1][1]), "r"(Ax[1][1][2]), "r"(Ax[1][1][3]),
                  "r"(r2), "r"(r3));
        }

        #pragma unroll
        for (int k2 = 0; k2 < 4; k2++) {
            unsigned r0, r1, r2, r3;
            asm volatile("ldmatrix.sync.aligned.m8n8.x4.shared.b16 {%0,%1,%2,%3}, [%4];"
                : "=r"(r0), "=r"(r1), "=r"(r2), "=r"(r3) : "r"(lm + k2 * 64));
            asm volatile("mma.sync.aligned.m16n8k16.row.col.f32.f16.f16.f32 "
                "{%0,%1,%2,%3}, {%4,%5,%6,%7}, {%8,%9}, {%0,%1,%2,%3};"
                : "+f"(c0[0]), "+f"(c0[1]), "+f"(c0[2]), "+f"(c0[3])
                : "r"(Af[2*k2][0][0]), "r"(Af[2*k2][0][1]), "r"(Af[2*k2][0][2]), "r"(Af[2*k2][0][3]),
                  "r"(r0), "r"(r1));
            asm volatile("mma.sync.aligned.m16n8k16.row.col.f32.f16.f16.f32 "
                "{%0,%1,%2,%3}, {%4,%5,%6,%7}, {%8,%9}, {%0,%1,%2,%3};"
                : "+f"(c1[0]), "+f"(c1[1]), "+f"(c1[2]), "+f"(c1[3])
                : "r"(Af[2*k2][1][0]), "r"(Af[2*k2][1][1]), "r"(Af[2*k2][1][2]), "r"(Af[2*k2][1][3]),
                  "r"(r0), "r"(r1));
            asm volatile("mma.sync.aligned.m16n8k16.row.col.f32.f16.f16.f32 "
                "{%0,%1,%2,%3}, {%4,%5,%6,%7}, {%8,%9}, {%0,%1,%2,%3};"
                : "+f"(c0[0]), "+f"(c0[1]), "+f"(c0[2]), "+f"(c0[3])
                : "r"(Af[2*k2+1][0][0]), "r"(Af[2*k2+1][0][1]), "r"(Af[2*k2+1][0][2]), "r"(Af[2*k2+1][0][3]),
                  "r"(r2), "r"(r3));
            asm volatile("mma.sync.aligned.m16n8k16.row.col.f32.f16.f16.f32 "
                "{%0,%1,%2,%3}, {%4,%5,%6,%7}, {%8,%9}, {%0,%1,%2,%3};"
                : "+f"(c1[0]), "+f"(c1[1]), "+f"(c1[2]), "+f"(c1[3])
                : "r"(Af[2*k2+1][1][0]), "r"(Af[2*k2+1][1][1]), "r"(Af[2*k2+1][1][2]), "r"(Af[2*k2+1][1][3]),
                  "r"(r2), "r"(r3));
        }

        float ii0 = fmaf(tanhap(c0[0]), 0.5f, 0.5f);
        float ii1 = fmaf(tanhap(c0[1]), 0.5f, 0.5f);
        float ff0 = fmaf(tanhap(c0[2]), 0.5f, 0.5f);
        float ff1 = fmaf(tanhap(c0[3]), 0.5f, 0.5f);
        float gg0 = tanhap(c1[0]);
        float gg1 = tanhap(c1[1]);
        float oo0 = fmaf(tanhap(c1[2]), 0.5f, 0.5f);
        float oo1 = fmaf(tanhap(c1[3]), 0.5f, 0.5f);

        cst0 = fmaf(ff0, cst0, ii0 * gg0);
        cst1 = fmaf(ff1, cst1, ii1 * gg1);
        h0v = oo0 * tanhap(cst0);
        h1v = oo1 * tanhap(cst1);

        hw[(2 * tg)     * HAS_ + hc] = __float2half(h0v);
        hw[(2 * tg + 1) * HAS_ + hc] = __float2half(h1v);

        if (s + 1 < T_ && tid < 32) {
            asm volatile("cp.async.wait_group 0;");
        }
        __syncthreads();
    }

    // epilogue: write final step's y0 (h(T-1) in buf ((T-1)&1)^1 = 0)
    {
        int tp = dir ? 0 : (T_ - 1);
        __half2 hv = *(__half2*)&hA[0 * 8 * HAS_ + yr * HAS_ + yc];
        *(__half2*)&g_y0h[((size_t)tp * B_ + b0 + yr) * (2 * H_) + dir * H_ + yc] = hv;
    }

    const int d = dir;
    hn[((size_t)d * B_ + brow0) * H_ + hc] = h0v;
    hn[((size_t)d * B_ + brow1) * H_ + hc] = h1v;
    cn[((size_t)d * B_ + brow0) * H_ + hc] = cst0;
    cn[((size_t)d * B_ + brow1) * H_ + hc] = cst1;
}

// ---------------- layer-1 scan; fp32 ybuf + deferred cooperative y1 write ----------
__global__ __launch_bounds__(512) void lstm_scan_mma(
    const float* __restrict__ whhf, const float* __restrict__ whhb,
    float* __restrict__ y1, float* __restrict__ hn, float* __restrict__ cn)
{
    __shared__ __half hA[2 * 8 * HAS_];
    __shared__ float  ybuf[2 * 8 * YBS_];   // fp32 h staging (exact y1 values)

    const int tid  = threadIdx.x;
    const int lane = tid & 31;
    const int w    = tid >> 5;
    const int dir  = blockIdx.y;
    const int b0   = blockIdx.x * MB_;
    const int g4 = lane >> 2, tg = lane & 3;
    const float* __restrict__ whh = dir ? whhb : whhf;
    const float* __restrict__ gx  = g_gx[dir];

    unsigned Af[8][2][4];
    #pragma unroll
    for (int ks = 0; ks < 8; ks++)
        #pragma unroll
        for (int tl = 0; tl < 2; tl++) {
            const float* pA = whh + (size_t)((2 * tl)     * 128 + 8 * w + g4) * H_ + ks * 16 + tg * 2;
            const float* pB = whh + (size_t)((2 * tl + 1) * 128 + 8 * w + g4) * H_ + ks * 16 + tg * 2;
            float2 vA0 = *(const float2*)pA;
            float2 vB0 = *(const float2*)pB;
            float2 vA1 = *(const float2*)(pA + 8);
            float2 vB1 = *(const float2*)(pB + 8);
            __half2 h0 = __floats2half2_rn(vA0.x, vA0.y);
            __half2 h1 = __floats2half2_rn(vB0.x, vB0.y);
            __half2 h2 = __floats2half2_rn(vA1.x, vA1.y);
            __half2 h3 = __floats2half2_rn(vB1.x, vB1.y);
            Af[ks][tl][0] = *(unsigned*)&h0;
            Af[ks][tl][1] = *(unsigned*)&h1;
            Af[ks][tl][2] = *(unsigned*)&h2;
            Af[ks][tl][3] = *(unsigned*)&h3;
        }

    for (int p = tid; p < 2 * 8 * HAS_; p += 512) hA[p] = __float2half(0.f);

    const int hc    = 8 * w + g4;
    const int brow0 = b0 + 2 * tg;
    const int brow1 = brow0 + 1;
    float cst0 = 0.f, cst1 = 0.f;
    float h0 = 0.f, h1 = 0.f;

    const unsigned hA_base = (unsigned)__cvta_generic_to_shared(hA);
    const unsigned lmB4 = hA_base + (((lane & 7) * HAS_) + ((lane >> 3) & 3) * 8) * 2;
    const unsigned BUFB = 8 * HAS_ * 2;

    const int bg0 = b0 >> 3;
    const float* gxb = gx + 2 * tg;

    // deferred-write mapping: row = tid>>6, 2 float cols per thread
    const int yr = tid >> 6;
    const int yc = (tid & 63) * 2;

    __syncthreads();

    float2 xi, xf, xg, xo;
    {
        int t0 = dir ? (T_ - 1) : 0;
        const float* p = gxb + ((size_t)t0 * 32 + bg0) * G_ * 8;
        xi = *(const float2*)(p + (0 * 128 + hc) * 8);
        xf = *(const float2*)(p + (1 * 128 + hc) * 8);
        xg = *(const float2*)(p + (2 * 128 + hc) * 8);
        xo = *(const float2*)(p + (3 * 128 + hc) * 8);
    }

    for (int s = 0; s < T_; s++) {
        const int t = dir ? (T_ - 1 - s) : s;
        const int rb = s & 1;
        const unsigned lm = lmB4 + rb * BUFB;
        __half* hw = hA + (rb ^ 1) * 8 * HAS_;
        float* yw = ybuf + (rb ^ 1) * 8 * YBS_;

        float2 ni, nf2, ng, no;
        if (s + 1 < T_) {
            int tn = dir ? (T_ - 2 - s) : (s + 1);
            const float* p = gxb + ((size_t)tn * 32 + bg0) * G_ * 8;
            ni  = *(const float2*)(p + (0 * 128 + hc) * 8);
            nf2 = *(const float2*)(p + (1 * 128 + hc) * 8);
            ng  = *(const float2*)(p + (2 * 128 + hc) * 8);
            no  = *(const float2*)(p + (3 * 128 + hc) * 8);
        } else {
            ni = nf2 = ng = no = make_float2(0.f, 0.f);
        }

        // deferred y1 write: h(s-1) lives in ybuf buf rb
        if (s > 0) {
            int tp = dir ? (T_ - s) : (s - 1);
            float2 hv = *(float2*)&ybuf[rb * 8 * YBS_ + yr * YBS_ + yc];
            *(float2*)&y1[((size_t)(b0 + yr) * T_ + tp) * (2 * H_) + dir * H_ + yc] = hv;
        }

        float c0[4] = {0.f, 0.f, 0.f, 0.f};
        float c1[4] = {0.f, 0.f, 0.f, 0.f};

        #pragma unroll
        for (int k2 = 0; k2 < 4; k2++) {
            unsigned r0, r1, r2, r3;
            asm volatile("ldmatrix.sync.aligned.m8n8.x4.shared.b16 {%0,%1,%2,%3}, [%4];"
                : "=r"(r0), "=r"(r1), "=r"(r2), "=r"(r3) : "r"(lm + k2 * 64));
            asm volatile("mma.sync.aligned.m16n8k16.row.col.f32.f16.f16.f32 "
                "{%0,%1,%2,%3}, {%4,%5,%6,%7}, {%8,%9}, {%0,%1,%2,%3};"
                : "+f"(c0[0]), "+f"(c0[1]), "+f"(c0[2]), "+f"(c0[3])
                : "r"(Af[2*k2][0][0]), "r"(Af[2*k2][0][1]), "r"(Af[2*k2][0][2]), "r"(Af[2*k2][0][3]),
                  "r"(r0), "r"(r1));
            asm volatile("mma.sync.aligned.m16n8k16.row.col.f32.f16.f16.f32 "
                "{%0,%1,%2,%3}, {%4,%5,%6,%7}, {%8,%9}, {%0,%1,%2,%3};"
                : "+f"(c1[0]), "+f"(c1[1]), "+f"(c1[2]), "+f"(c1[3])
                : "r"(Af[2*k2][1][0]), "r"(Af[2*k2][1][1]), "r"(Af[2*k2][1][2]), "r"(Af[2*k2][1][3]),
                  "r"(r0), "r"(r1));
            asm volatile("mma.sync.aligned.m16n8k16.row.col.f32.f16.f16.f32 "
                "{%0,%1,%2,%3}, {%4,%5,%6,%7}, {%8,%9}, {%0,%1,%2,%3};"
                : "+f"(c0[0]), "+f"(c0[1]), "+f"(c0[2]), "+f"(c0[3])
                : "r"(Af[2*k2+1][0][0]), "r"(Af[2*k2+1][0][1]), "r"(Af[2*k2+1][0][2]), "r"(Af[2*k2+1][0][3]),
                  "r"(r2), "r"(r3));
            asm volatile("mma.sync.aligned.m16n8k16.row.col.f32.f16.f16.f32 "
                "{%0,%1,%2,%3}, {%4,%5,%6,%7}, {%8,%9}, {%0,%1,%2,%3};"
                : "+f"(c1[0]), "+f"(c1[1]), "+f"(c1[2]), "+f"(c1[3])
                : "r"(Af[2*k2+1][1][0]), "r"(Af[2*k2+1][1][1]), "r"(Af[2*k2+1][1][2]), "r"(Af[2*k2+1][1][3]),
                  "r"(r2), "r"(r3));
        }

        float ii0 = fmaf(tanhap(fmaf(c0[0], 0.5f, xi.x)), 0.5f, 0.5f);
        float ii1 = fmaf(tanhap(fmaf(c0[1], 0.5f, xi.y)), 0.5f, 0.5f);
        float ff0 = fmaf(tanhap(fmaf(c0[2], 0.5f, xf.x)), 0.5f, 0.5f);
        float ff1 = fmaf(tanhap(fmaf(c0[3], 0.5f, xf.y)), 0.5f, 0.5f);
        float gg0 = tanhap(c1[0] + xg.x);
        float gg1 = tanhap(c1[1] + xg.y);
        float oo0 = fmaf(tanhap(fmaf(c1[2], 0.5f, xo.x)), 0.5f, 0.5f);
        float oo1 = fmaf(tanhap(fmaf(c1[3], 0.5f, xo.y)), 0.5f, 0.5f);

        cst0 = fmaf(ff0, cst0, ii0 * gg0);
        cst1 = fmaf(ff1, cst1, ii1 * gg1);
        h0 = oo0 * tanhap(cst0);
        h1 = oo1 * tanhap(cst1);

        hw[(2 * tg)     * HAS_ + hc] = __float2half(h0);
        hw[(2 * tg + 1) * HAS_ + hc] = __float2half(h1);
        yw[(2 * tg)     * YBS_ + hc] = h0;
        yw[(2 * tg + 1) * YBS_ + hc] = h1;

        xi = ni; xf = nf2; xg = ng; xo = no;
        __syncthreads();
    }

    // epilogue: final step's y1 (h(T-1) in ybuf buf 0)
    {
        int tp = dir ? 0 : (T_ - 1);
        float2 hv = *(float2*)&ybuf[0 * 8 * YBS_ + yr * YBS_ + yc];
        *(float2*)&y1[((size_t)(b0 + yr) * T_ + tp) * (2 * H_) + dir * H_ + yc] = hv;
    }

    const int d = 2 + dir;   // layer 1
    hn[((size_t)d * B_ + brow0) * H_ + hc] = h0;
    hn[((size_t)d * B_ + brow1) * H_ + hc] = h1;
    cn[((size_t)d * B_ + brow0) * H_ + hc] = cst0;
    cn[((size_t)d * B_ + brow1) * H_ + hc] = cst1;
}

// ---------------- launch ----------------
extern "C" void kernel_launch(void* const* d_in, const int* in_sizes, int n_in,
                              void* d_out, int out_size) {
    const float* x     = (const float*)d_in[0];
    const float* wih0f = (const float*)d_in[1];
    const float* whh0f = (const float*)d_in[2];
    const float* b0f   = (const float*)d_in[3];
    const float* wih0b = (const float*)d_in[4];
    const float* whh0b = (const float*)d_in[5];
    const float* b0b   = (const float*)d_in[6];
    const float* wih1f = (const float*)d_in[7];
    const float* whh1f = (const float*)d_in[8];
    const float* b1f   = (const float*)d_in[9];
    const float* wih1b = (const float*)d_in[10];
    const float* whh1b = (const float*)d_in[11];
    const float* b1b   = (const float*)d_in[12];
    (void)in_sizes; (void)n_in; (void)out_size;

    float* out = (float*)d_out;
    float* y1 = out;
    float* hn = out + Y1SZ_;
    float* cn = hn + 4 * B_ * H_;

    // fp16 conversions
    conv_x_kernel<<<(BT_ * 32 + 255) / 256, 256>>>(x);
    conv_w1_kernel<<<(2 * G_ * 256 + 255) / 256, 256>>>(wih1f, wih1b);

    // layer 0: fused input-GEMM + scan
    lstm_scan_fused0<<<dim3(B_ / MB_, 2), 512>>>(wih0f, whh0f, b0f, wih0b, whh0b, b0b, hn, cn);

    // layer 1
    gemm_gx_kernel<<<dim3(8, BT_ / 128), 256>>>(b1f, b1b);
    lstm_scan_mma<<<dim3(B_ / MB_, 2), 512>>>(whh1f, whh1b, y1, hn, cn);
}